// round 13
// baseline (speedup 1.0000x reference)
#include <cuda_runtime.h>
#include <cuda_bf16.h>
#include <math.h>
#include <stdint.h>

#define NB   64
#define NI   1024
#define NHID 2048
#define NH   8
#define ND   256
#define EPS  1e-5f

// ---------------- device scratch ----------------
__device__ float g_xn[NB * NI];
__device__ float g_xl[NB * NHID];
__device__ float g_xr[NB * NHID];
__device__ float g_xc[NB * NHID];
__device__ float g_xskip[NB * NHID];
__device__ float g_o[NB * NHID];
__device__ float g_q[NB * NHID];
__device__ float g_k[NB * NHID];
__device__ float g_v[NB * NHID];
__device__ float g_outpre[NB * NHID];
__device__ float g_ig[NB * NH];
__device__ float g_fg[NB * NH];
__device__ float g_part[24 * NB * NHID];        // split-K partial slots (12.6MB)

// ---------------- helpers ----------------
__device__ __forceinline__ float blockReduce256(float v) {
    __shared__ float red[256];
    int t = threadIdx.x;
    red[t] = v;
    __syncthreads();
#pragma unroll
    for (int s = 128; s > 0; s >>= 1) {
        if (t < s) red[t] += red[t + s];
        __syncthreads();
    }
    float r = red[0];
    __syncthreads();
    return r;
}
__device__ __forceinline__ float sigmoidf_(float x) { return 1.f / (1.f + expf(-x)); }
__device__ __forceinline__ float siluf_(float x) { return x / (1.f + expf(-x)); }

// split a float pair into bf16x2 hi and lo words (low half = first element)
__device__ __forceinline__ void pack_hl(float x, float y, uint32_t& hi, uint32_t& lo) {
    __nv_bfloat162 h = __float22bfloat162_rn(make_float2(x, y));
    float2 hf = __bfloat1622float2(h);
    __nv_bfloat162 l = __float22bfloat162_rn(make_float2(x - hf.x, y - hf.y));
    hi = *(uint32_t*)&h;
    lo = *(uint32_t*)&l;
}

__device__ __forceinline__ void mma_bf16(float* acc, uint32_t a0, uint32_t a1,
                                         uint32_t a2, uint32_t a3,
                                         uint32_t b0, uint32_t b1) {
    asm volatile(
        "mma.sync.aligned.m16n8k16.row.col.f32.bf16.bf16.f32 "
        "{%0,%1,%2,%3}, {%4,%5,%6,%7}, {%8,%9}, {%0,%1,%2,%3};"
        : "+f"(acc[0]), "+f"(acc[1]), "+f"(acc[2]), "+f"(acc[3])
        : "r"(a0), "r"(a1), "r"(a2), "r"(a3), "r"(b0), "r"(b1));
}

__device__ __forceinline__ void cpasync4(uint32_t smem_addr, const float* gptr) {
    asm volatile("cp.async.ca.shared.global [%0], [%1], 4;" :: "r"(smem_addr), "l"(gptr));
}
#define CP_COMMIT() asm volatile("cp.async.commit_group;" ::: "memory")
#define CP_WAIT0()  asm volatile("cp.async.wait_group 0;" ::: "memory")

// ---------------- LayerNorm ----------------
__global__ __launch_bounds__(256) void ln_kernel(const float* __restrict__ x,
                                                 const float* __restrict__ w,
                                                 const float* __restrict__ b) {
    int bi = blockIdx.x, t = threadIdx.x;
    const float* xr = x + bi * NI;
    float vals[4];
    float s = 0.f;
#pragma unroll
    for (int i = 0; i < 4; i++) { vals[i] = xr[t + 256 * i]; s += vals[i]; }
    float mu = blockReduce256(s) * (1.f / NI);
    float s2 = 0.f;
#pragma unroll
    for (int i = 0; i < 4; i++) { float d = vals[i] - mu; s2 += d * d; }
    float var = blockReduce256(s2) * (1.f / NI);
    float rs = rsqrtf(var + EPS);
#pragma unroll
    for (int i = 0; i < 4; i++) {
        int c = t + 256 * i;
        g_xn[bi * NI + c] = (vals[i] - mu) * rs * w[c] + b[c];
    }
}

// ---------------- tensor-core split-K GEMM: 64(M) x 128(N) tile, double-buffered ----
// wfmt=0: W fp32 [K][N] (register prefetch path)
// wfmt=1: conv tap-3 — W element (k,n) at W[(n*2048+k)*4+3], streamed via cp.async
struct GJob {
    const float* A; const float* W;
    float* P;
    int K, kc, N, wfmt;
};

// dynamic smem layout (uint32 words):
//  Aph [2][16][72]  @ 0      (2304)
//  Apl [2][16][72]  @ 2304
//  Wph [2][16][136] @ 4608   (4352)
//  Wpl [2][16][136] @ 8960
//  raw [2][32][128] @ 13312  (8192)  -- conv cp.async staging (floats)
#define RAW_OFF 13312
#define SMEM_WORDS (13312 + 8192)

__global__ __launch_bounds__(256, 2) void gemm_t(GJob j0, GJob j1, GJob j2) {
    GJob j = (blockIdx.z == 0) ? j0 : (blockIdx.z == 1 ? j1 : j2);
    extern __shared__ __align__(16) uint32_t sm[];
    typedef uint32_t (*A72)[72];
    typedef uint32_t (*W136)[136];

    const int tid = threadIdx.x;
    const int n0 = blockIdx.x * 128;
    const int k0 = blockIdx.y * j.kc;
    const int nst = j.kc >> 5;
    float* P = j.P + (size_t)blockIdx.y * 64 * j.N;

    const int lane = tid & 31;
    const int warp = tid >> 5;
    const int g = lane >> 2, tg = lane & 3;
    const int wm = warp & 3, wn = warp >> 2;     // 4 warps M x 2 warps N

    // A staging map: m = tid>>2, k-offset = (tid&3)*8
    const int am = tid >> 2;
    const int ak = (tid & 3) * 8;

    const uint32_t smb = (uint32_t)__cvta_generic_to_shared(sm);

    float4 av0, av1;
    float wv[16];
    float acc[8][4] = {};

    // ---- load stage (gmem -> regs / async smem) ----
    auto load = [&](int kb, int buf) {
        const float* Ap = j.A + (size_t)am * j.K + kb + ak;
        av0 = *(const float4*)(Ap);
        av1 = *(const float4*)(Ap + 4);
        if (j.wfmt == 0) {
#pragma unroll
            for (int r = 0; r < 2; r++) {
                int e = tid + r * 256;
                int kp = e >> 5, n4 = e & 31;
                float4 r0 = *(const float4*)(j.W + (size_t)(kb + 2 * kp) * j.N + n0 + n4 * 4);
                float4 r1 = *(const float4*)(j.W + (size_t)(kb + 2 * kp + 1) * j.N + n0 + n4 * 4);
                wv[r * 8 + 0] = r0.x; wv[r * 8 + 1] = r0.y; wv[r * 8 + 2] = r0.z; wv[r * 8 + 3] = r0.w;
                wv[r * 8 + 4] = r1.x; wv[r * 8 + 5] = r1.y; wv[r * 8 + 6] = r1.z; wv[r * 8 + 7] = r1.w;
            }
        } else {
            // fire-and-forget 4B cp.async: lane = k, 16 n-rows per thread
            uint32_t rbase = smb + (RAW_OFF + buf * 4096) * 4;
            const float* base = j.W + 3 + (size_t)(kb + lane) * 4;
#pragma unroll
            for (int i = 0; i < 16; i++) {
                int n = warp * 16 + i;
                cpasync4(rbase + (uint32_t)(lane * 128 + n) * 4,
                         base + (size_t)(n0 + n) * 8192);
            }
            CP_COMMIT();
        }
    };

    // ---- store stage (regs/raw smem -> packed smem buffer) ----
    auto store = [&](int buf) {
        A72 aph = (A72)(sm + buf * 16 * 72);
        A72 apl = (A72)(sm + 2304 + buf * 16 * 72);
        W136 wph = (W136)(sm + 4608 + buf * 16 * 136);
        W136 wpl = (W136)(sm + 8960 + buf * 16 * 136);
        int p0 = ak >> 1;
        pack_hl(av0.x, av0.y, aph[p0 + 0][am], apl[p0 + 0][am]);
        pack_hl(av0.z, av0.w, aph[p0 + 1][am], apl[p0 + 1][am]);
        pack_hl(av1.x, av1.y, aph[p0 + 2][am], apl[p0 + 2][am]);
        pack_hl(av1.z, av1.w, aph[p0 + 3][am], apl[p0 + 3][am]);
        if (j.wfmt == 0) {
#pragma unroll
            for (int r = 0; r < 2; r++) {
                int e = tid + r * 256;
                int kp = e >> 5, n4 = e & 31;
                uint4 hi, lo;
                pack_hl(wv[r * 8 + 0], wv[r * 8 + 4], hi.x, lo.x);
                pack_hl(wv[r * 8 + 1], wv[r * 8 + 5], hi.y, lo.y);
                pack_hl(wv[r * 8 + 2], wv[r * 8 + 6], hi.z, lo.z);
                pack_hl(wv[r * 8 + 3], wv[r * 8 + 7], hi.w, lo.w);
                *(uint4*)&wph[kp][n4 * 4] = hi;
                *(uint4*)&wpl[kp][n4 * 4] = lo;
            }
        } else {
            const float* raw = (const float*)(sm + RAW_OFF + buf * 4096);
#pragma unroll
            for (int r = 0; r < 8; r++) {
                int e = tid + r * 256;
                int n = e & 127, kp = e >> 7;      // n fastest -> conflict-free LDS/STS
                float v0 = raw[(2 * kp) * 128 + n];
                float v1 = raw[(2 * kp + 1) * 128 + n];
                pack_hl(v0, v1, wph[kp][n], wpl[kp][n]);
            }
        }
    };

    // ---- compute on a packed smem buffer ----
    auto compute = [&](int buf) {
        A72 aph = (A72)(sm + buf * 16 * 72);
        A72 apl = (A72)(sm + 2304 + buf * 16 * 72);
        W136 wph = (W136)(sm + 4608 + buf * 16 * 136);
        W136 wpl = (W136)(sm + 8960 + buf * 16 * 136);
#pragma unroll
        for (int st = 0; st < 2; st++) {
            int kr = st * 8;
            int mrow = wm * 16 + g;
            uint32_t a0h = aph[kr + tg][mrow];
            uint32_t a1h = aph[kr + tg][mrow + 8];
            uint32_t a2h = aph[kr + tg + 4][mrow];
            uint32_t a3h = aph[kr + tg + 4][mrow + 8];
            uint32_t a0l = apl[kr + tg][mrow];
            uint32_t a1l = apl[kr + tg][mrow + 8];
            uint32_t a2l = apl[kr + tg + 4][mrow];
            uint32_t a3l = apl[kr + tg + 4][mrow + 8];
#pragma unroll
            for (int jt = 0; jt < 8; jt++) {
                int col = wn * 64 + jt * 8 + g;
                uint32_t b0h = wph[kr + tg][col];
                uint32_t b1h = wph[kr + tg + 4][col];
                uint32_t b0l = wpl[kr + tg][col];
                uint32_t b1l = wpl[kr + tg + 4][col];
                mma_bf16(acc[jt], a0h, a1h, a2h, a3h, b0h, b1h);
                mma_bf16(acc[jt], a0h, a1h, a2h, a3h, b0l, b1l);
                mma_bf16(acc[jt], a0l, a1l, a2l, a3l, b0h, b1h);
            }
        }
    };

    load(k0, 0);
    if (j.wfmt == 1) { CP_WAIT0(); __syncthreads(); }
    store(0);
    __syncthreads();
    for (int s = 0; s < nst; s++) {
        if (s + 1 < nst) load(k0 + (s + 1) * 32, (s + 1) & 1);
        compute(s & 1);
        if (s + 1 < nst) {
            if (j.wfmt == 1) { CP_WAIT0(); __syncthreads(); }
            store((s + 1) & 1);
            __syncthreads();
        }
    }

    // ---- write partials ----
#pragma unroll
    for (int jt = 0; jt < 8; jt++) {
        int col = n0 + wn * 64 + jt * 8 + tg * 2;
        int row0 = wm * 16 + g;
        *(float2*)(P + (size_t)row0 * j.N + col) = make_float2(acc[jt][0], acc[jt][1]);
        *(float2*)(P + (size_t)(row0 + 8) * j.N + col) = make_float2(acc[jt][2], acc[jt][3]);
    }
}

// ---------------- float4 split-K reduce + epilogue, tri-job ----------------
struct RJob {
    const float4* P; int np;
    const float4* bias; float4* C;
    int mode; const float4* R; int N4;
};

__global__ __launch_bounds__(256) void reduce_k(RJob r0, RJob r1, RJob r2) {
    RJob r = (blockIdx.z == 0) ? r0 : (blockIdx.z == 1 ? r1 : r2);
    int idx = blockIdx.x * 256 + threadIdx.x;
    int total = 64 * r.N4;
    if (idx >= total) return;
    int n4 = idx % r.N4;
    float4 s = make_float4(0.f, 0.f, 0.f, 0.f);
#pragma unroll 8
    for (int p = 0; p < r.np; p++) {
        float4 v = r.P[(size_t)p * total + idx];
        s.x += v.x; s.y += v.y; s.z += v.z; s.w += v.w;
    }
    float4 b = r.bias[n4];
    s.x += b.x; s.y += b.y; s.z += b.z; s.w += b.w;
    if (r.mode == 1) {
        s.x = siluf_(s.x); s.y = siluf_(s.y); s.z = siluf_(s.z); s.w = siluf_(s.w);
    } else if (r.mode == 2) {
        s.x = sigmoidf_(s.x); s.y = sigmoidf_(s.y); s.z = sigmoidf_(s.z); s.w = sigmoidf_(s.w);
    } else if (r.mode == 3) {
        float4 rv = r.R[idx];
        s.x += rv.x; s.y += rv.y; s.z += rv.z; s.w += rv.w;
    }
    r.C[idx] = s;
}

// ---------------- block-diagonal q/k/v GEMMs + fused i/f gates ----------------
// grid (4, 2, 32): z<24 -> qkv (which=z>>3, h=z&7, 32x64 tile); z>=24 -> gates for
// batch b = (z-24)*8 + blockIdx.y*4 + blockIdx.x. 128 threads.
__global__ __launch_bounds__(128) void qkv_kernel(const float* __restrict__ Wq,
                                                  const float* __restrict__ Wk,
                                                  const float* __restrict__ Wv,
                                                  const float* __restrict__ bq,
                                                  const float* __restrict__ bk,
                                                  const float* __restrict__ bv,
                                                  const float* __restrict__ Wi,
                                                  const float* __restrict__ bi,
                                                  const float* __restrict__ Wf,
                                                  const float* __restrict__ bf,
                                                  const float* __restrict__ m_prev,
                                                  float* __restrict__ m_out) {
    int z = blockIdx.z;
    if (z >= 24) {
        int b = (z - 24) * 8 + blockIdx.y * 4 + blockIdx.x;
        int t = threadIdx.x;
        float pi[8] = {}, pf[8] = {};
        for (int k = t; k < NHID; k += 128) {
            float xv = g_xc[b * NHID + k];
            const float4* wi4 = (const float4*)(Wi + k * 8);
            const float4* wf4 = (const float4*)(Wf + k * 8);
            float4 a0 = wi4[0], a1 = wi4[1], f0 = wf4[0], f1 = wf4[1];
            pi[0] += xv * a0.x; pi[1] += xv * a0.y; pi[2] += xv * a0.z; pi[3] += xv * a0.w;
            pi[4] += xv * a1.x; pi[5] += xv * a1.y; pi[6] += xv * a1.z; pi[7] += xv * a1.w;
            pf[0] += xv * f0.x; pf[1] += xv * f0.y; pf[2] += xv * f0.z; pf[3] += xv * f0.w;
            pf[4] += xv * f1.x; pf[5] += xv * f1.y; pf[6] += xv * f1.z; pf[7] += xv * f1.w;
        }
        __shared__ float s[128 * 16];
#pragma unroll
        for (int h = 0; h < 8; h++) { s[t * 16 + h] = pi[h]; s[t * 16 + 8 + h] = pf[h]; }
        __syncthreads();
        if (t < 16) {
            float a = 0.f;
            for (int r = 0; r < 128; r++) a += s[r * 16 + t];
            s[t] = a;
        }
        __syncthreads();
        if (t < 8) {
            float it = s[t] + bi[t];
            float ft = s[8 + t] + bf[t];
            float mp = m_prev[b * 8 + t];
            float m = fmaxf(ft + mp, it);
            m_out[b * 8 + t] = m;
            g_ig[b * 8 + t] = expf(it - m);
            g_fg[b * 8 + t] = expf(ft + mp - m);
        }
        return;
    }
    int which = z >> 3, h = z & 7;
    const float* A = (which == 2) ? g_xl : g_xc;
    const float* W; const float* bias; float* C; float scale = 1.f;
    if (which == 0) { W = Wq; bias = bq; C = g_q; }
    else if (which == 1) { W = Wk; bias = bk; C = g_k; scale = 0.0625f; }
    else { W = Wv; bias = bv; C = g_v; }
    W += (size_t)h * ND * ND;
    bias += h * ND;
    int n0 = blockIdx.x * 64;
    int m0 = blockIdx.y * 32;
    __shared__ __align__(16) float As[32][36];
    __shared__ __align__(16) float Ws[32][68];
    int tx = threadIdx.x & 15, ty = threadIdx.x >> 4;
    float acc[4][4] = {};
    for (int kb = 0; kb < ND; kb += 32) {
#pragma unroll
        for (int r = 0; r < 2; r++) {
            int ee = threadIdx.x + r * 128;
            int k4 = ee & 7, m = ee >> 3;
            float4 v = *(const float4*)(A + (size_t)(m0 + m) * NHID + h * ND + kb + 4 * k4);
            *(float4*)&As[m][4 * k4] = v;
        }
#pragma unroll
        for (int r = 0; r < 4; r++) {
            int ee = threadIdx.x + r * 128;
            int n4 = ee & 15, k = ee >> 4;
            float4 v = *(const float4*)(W + (size_t)(kb + k) * ND + n0 + 4 * n4);
            *(float4*)&Ws[k][4 * n4] = v;
        }
        __syncthreads();
#pragma unroll
        for (int kk = 0; kk < 32; kk++) {
            float4 w = *(const float4*)&Ws[kk][tx * 4];
            float a0 = As[ty * 4 + 0][kk];
            float a1 = As[ty * 4 + 1][kk];
            float a2 = As[ty * 4 + 2][kk];
            float a3 = As[ty * 4 + 3][kk];
            acc[0][0] += a0 * w.x; acc[0][1] += a0 * w.y; acc[0][2] += a0 * w.z; acc[0][3] += a0 * w.w;
            acc[1][0] += a1 * w.x; acc[1][1] += a1 * w.y; acc[1][2] += a1 * w.z; acc[1][3] += a1 * w.w;
            acc[2][0] += a2 * w.x; acc[2][1] += a2 * w.y; acc[2][2] += a2 * w.z; acc[2][3] += a2 * w.w;
            acc[3][0] += a3 * w.x; acc[3][1] += a3 * w.y; acc[3][2] += a3 * w.z; acc[3][3] += a3 * w.w;
        }
        __syncthreads();
    }
#pragma unroll
    for (int i = 0; i < 4; i++) {
        int m = m0 + ty * 4 + i;
        int n = n0 + tx * 4;
        float4 b4 = *(const float4*)(bias + n);
        float4 v = make_float4((acc[i][0] + b4.x) * scale, (acc[i][1] + b4.y) * scale,
                               (acc[i][2] + b4.z) * scale, (acc[i][3] + b4.w) * scale);
        *(float4*)(C + (size_t)m * NHID + h * ND + n) = v;
    }
}

// ---------------- fused state update + readout + GroupNorm + gating ----------------
__global__ __launch_bounds__(256) void state_kernel(const float* __restrict__ c_prev,
                                                    const float* __restrict__ n_prev,
                                                    const float* __restrict__ gn_w,
                                                    const float* __restrict__ gn_b,
                                                    float* __restrict__ c_out,
                                                    float* __restrict__ n_out,
                                                    float* __restrict__ h_out) {
    int bh = blockIdx.x;
    int b = bh >> 3, h = bh & 7;
    int t = threadIdx.x;
    __shared__ __align__(16) float qs[256], ks[256], vs[256], hts[256];
    __shared__ float den_s;
    float fg = g_fg[bh], ig = g_ig[bh];
    int base = bh * ND;
    float qv = g_q[base + t], kv = g_k[base + t], vv = g_v[base + t];
    qs[t] = qv; ks[t] = kv; vs[t] = vv;
    float nt = fg * n_prev[base + t] + ig * kv;
    n_out[base + t] = nt;
    float den = blockReduce256(nt * qv);
    if (t == 0) den_s = fmaxf(den, 1.f);
    __syncthreads();
    den = den_s;
    int w = t >> 5, lane = t & 31;
    const float4* cp4 = (const float4*)(c_prev + (size_t)bh * ND * ND);
    float4* ct4 = (float4*)(c_out + (size_t)bh * ND * ND);
    const float4* qs4 = (const float4*)qs;
    const float4* ks4 = (const float4*)ks;
    for (int d0 = w * 32; d0 < w * 32 + 32; d0 += 4) {
        float acc0 = 0.f, acc1 = 0.f, acc2 = 0.f, acc3 = 0.f;
        float vd0 = vs[d0 + 0] * ig, vd1 = vs[d0 + 1] * ig;
        float vd2 = vs[d0 + 2] * ig, vd3 = vs[d0 + 3] * ig;
#pragma unroll
        for (int p = 0; p < 2; p++) {
            int ci = lane + p * 32;
            float4 kk = ks4[ci];
            float4 qq = qs4[ci];
            float4 cp0 = cp4[(size_t)(d0 + 0) * 64 + ci];
            float4 cp1 = cp4[(size_t)(d0 + 1) * 64 + ci];
            float4 cp2 = cp4[(size_t)(d0 + 2) * 64 + ci];
            float4 cp3 = cp4[(size_t)(d0 + 3) * 64 + ci];
            float4 c0, c1, c2, c3;
            c0.x = fg * cp0.x + vd0 * kk.x; c0.y = fg * cp0.y + vd0 * kk.y;
            c0.z = fg * cp0.z + vd0 * kk.z; c0.w = fg * cp0.w + vd0 * kk.w;
            c1.x = fg * cp1.x + vd1 * kk.x; c1.y = fg * cp1.y + vd1 * kk.y;
            c1.z = fg * cp1.z + vd1 * kk.z; c1.w = fg * cp1.w + vd1 * kk.w;
            c2.x = fg * cp2.x + vd2 * kk.x; c2.y = fg * cp2.y + vd2 * kk.y;
            c2.z = fg * cp2.z + vd2 * kk.z; c2.w = fg * cp2.w + vd2 * kk.w;
            c3.x = fg * cp3.x + vd3 * kk.x; c3.y = fg * cp3.y + vd3 * kk.y;
            c3.z = fg * cp3.z + vd3 * kk.z; c3.w = fg * cp3.w + vd3 * kk.w;
            ct4[(size_t)(d0 + 0) * 64 + ci] = c0;
            ct4[(size_t)(d0 + 1) * 64 + ci] = c1;
            ct4[(size_t)(d0 + 2) * 64 + ci] = c2;
            ct4[(size_t)(d0 + 3) * 64 + ci] = c3;
            acc0 += c0.x * qq.x + c0.y * qq.y + c0.z * qq.z + c0.w * qq.w;
            acc1 += c1.x * qq.x + c1.y * qq.y + c1.z * qq.z + c1.w * qq.w;
            acc2 += c2.x * qq.x + c2.y * qq.y + c2.z * qq.z + c2.w * qq.w;
            acc3 += c3.x * qq.x + c3.y * qq.y + c3.z * qq.z + c3.w * qq.w;
        }
#pragma unroll
        for (int off = 16; off > 0; off >>= 1) {
            acc0 += __shfl_xor_sync(0xffffffffu, acc0, off);
            acc1 += __shfl_xor_sync(0xffffffffu, acc1, off);
            acc2 += __shfl_xor_sync(0xffffffffu, acc2, off);
            acc3 += __shfl_xor_sync(0xffffffffu, acc3, off);
        }
        if (lane == 0) {
            float h0 = g_o[base + d0 + 0] * acc0 / den;
            float h1 = g_o[base + d0 + 1] * acc1 / den;
            float h2 = g_o[base + d0 + 2] * acc2 / den;
            float h3 = g_o[base + d0 + 3] * acc3 / den;
            hts[d0 + 0] = h0; hts[d0 + 1] = h1; hts[d0 + 2] = h2; hts[d0 + 3] = h3;
            h_out[base + d0 + 0] = h0; h_out[base + d0 + 1] = h1;
            h_out[base + d0 + 2] = h2; h_out[base + d0 + 3] = h3;
        }
    }
    __syncthreads();
    float hv = hts[t];
    float mu = blockReduce256(hv) * (1.f / ND);
    float dv = hv - mu;
    float var = blockReduce256(dv * dv) * (1.f / ND);
    float g = dv * rsqrtf(var + EPS);
    int hid = h * ND + t;
    float xrv = g_xr[b * NHID + hid];
    g_outpre[b * NHID + hid] =
        (g * gn_w[hid] + gn_b[hid] + g_xskip[b * NHID + hid]) * siluf_(xrv);
}

// ---------------- host launcher ----------------
extern "C" void kernel_launch(void* const* d_in, const int* in_sizes, int n_in,
                              void* d_out, int out_size) {
    (void)in_sizes; (void)n_in; (void)out_size;
    const float* x      = (const float*)d_in[0];
    const float* c_prev = (const float*)d_in[2];
    const float* n_prev = (const float*)d_in[3];
    const float* m_prev = (const float*)d_in[4];
    const float* ln_w   = (const float*)d_in[5];
    const float* ln_b   = (const float*)d_in[6];
    const float* W_ul   = (const float*)d_in[7];
    const float* b_ul   = (const float*)d_in[8];
    const float* W_ur   = (const float*)d_in[9];
    const float* b_ur   = (const float*)d_in[10];
    const float* W_conv = (const float*)d_in[11];
    const float* b_conv = (const float*)d_in[12];
    const float* W_skip = (const float*)d_in[13];
    const float* b_skip = (const float*)d_in[14];
    const float* W_q    = (const float*)d_in[15];
    const float* b_q    = (const float*)d_in[16];
    const float* W_k    = (const float*)d_in[17];
    const float* b_k    = (const float*)d_in[18];
    const float* W_v    = (const float*)d_in[19];
    const float* b_v    = (const float*)d_in[20];
    const float* W_i    = (const float*)d_in[21];
    const float* b_i    = (const float*)d_in[22];
    const float* W_f    = (const float*)d_in[23];
    const float* b_f    = (const float*)d_in[24];
    const float* W_o    = (const float*)d_in[25];
    const float* b_o    = (const float*)d_in[26];
    const float* W_down = (const float*)d_in[27];
    const float* b_down = (const float*)d_in[28];
    const float* gn_w   = (const float*)d_in[29];
    const float* gn_b   = (const float*)d_in[30];

    float* out = (float*)d_out;
    float* out_final = out;
    float* out_h = out + NB * NI;
    float* out_c = out_h + NB * NH * ND;
    float* out_n = out_c + (size_t)NB * NH * ND * ND;
    float* out_m = out_n + NB * NH * ND;

    void *p_xn, *p_xl, *p_xr, *p_xc, *p_xskip, *p_o, *p_outpre, *p_part;
    cudaGetSymbolAddress(&p_xn, g_xn);
    cudaGetSymbolAddress(&p_xl, g_xl);
    cudaGetSymbolAddress(&p_xr, g_xr);
    cudaGetSymbolAddress(&p_xc, g_xc);
    cudaGetSymbolAddress(&p_xskip, g_xskip);
    cudaGetSymbolAddress(&p_o, g_o);
    cudaGetSymbolAddress(&p_outpre, g_outpre);
    cudaGetSymbolAddress(&p_part, g_part);
    float* xn = (float*)p_xn;
    float* xl = (float*)p_xl;
    float* xr = (float*)p_xr;
    float* xc = (float*)p_xc;
    float* xskip = (float*)p_xskip;
    float* o = (float*)p_o;
    float* outpre = (float*)p_outpre;
    float* part = (float*)p_part;

    const int SLOT = NB * NHID;   // 131072 floats per [64 x 2048] partial slot
    const int SMEM_BYTES = SMEM_WORDS * 4;   // 86016
    cudaFuncSetAttribute(gemm_t, cudaFuncAttributeMaxDynamicSharedMemorySize, SMEM_BYTES);

    // 1. LayerNorm
    ln_kernel<<<NB, 256>>>(x, ln_w, ln_b);

    // 2. xl = xn@W_ul : K=1024, 16-way split (grid 256 = 1 full wave)
    {
        GJob a{xn, W_ul, part, NI, 64, NHID, 0};
        gemm_t<<<dim3(16, 16, 1), 256, SMEM_BYTES>>>(a, a, a);
        RJob ra{(const float4*)part, 16, (const float4*)b_ul, (float4*)xl, 0, nullptr, NHID / 4};
        reduce_k<<<dim3(128, 1, 1), 256>>>(ra, ra, ra);
    }

    // 3. conv (tap-3 via cp.async) + ur : z=2, 256 blocks = 1 wave
    {
        GJob a{xl, W_conv, part, NHID, 256, NHID, 1};                      // slots 0-7
        GJob c3{xn, W_ur, part + (size_t)16 * SLOT, NI, 128, NHID, 0};     // slots 16-23
        gemm_t<<<dim3(16, 8, 2), 256, SMEM_BYTES>>>(a, c3, c3);
        RJob ra{(const float4*)part, 8, (const float4*)b_conv, (float4*)xc, 1, nullptr, NHID / 4};
        RJob rc{(const float4*)(part + (size_t)16 * SLOT), 8, (const float4*)b_ur, (float4*)xr, 0, nullptr, NHID / 4};
        reduce_k<<<dim3(128, 1, 2), 256>>>(ra, rc, rc);
    }

    // 4. skip + o-pre (both K=2048, 8-way) + qkv(+gates) ; then dual reduce
    {
        GJob a{xc, W_skip, part, NHID, 256, NHID, 0};                      // slots 0-7
        GJob b2{xl, W_o, part + (size_t)8 * SLOT, NHID, 256, NHID, 0};     // slots 8-15
        gemm_t<<<dim3(16, 8, 2), 256, SMEM_BYTES>>>(a, b2, b2);
        qkv_kernel<<<dim3(4, 2, 32), 128>>>(W_q, W_k, W_v, b_q, b_k, b_v,
                                            W_i, b_i, W_f, b_f, m_prev, out_m);
        RJob ra{(const float4*)part, 8, (const float4*)b_skip, (float4*)xskip, 0, nullptr, NHID / 4};
        RJob rb{(const float4*)(part + (size_t)8 * SLOT), 8, (const float4*)b_o, (float4*)o, 2, nullptr, NHID / 4};
        reduce_k<<<dim3(128, 1, 2), 256>>>(ra, rb, rb);
    }

    // 5. fused state update / readout / groupnorm / gating
    state_kernel<<<NB * NH, 256>>>(c_prev, n_prev, gn_w, gn_b, out_c, out_n, out_h);

    // 6. final = outpre @ W_down + b_down + x : K=2048, 32-way split, N=1024
    {
        GJob a{outpre, W_down, part, NHID, 64, NI, 0};
        gemm_t<<<dim3(8, 32, 1), 256, SMEM_BYTES>>>(a, a, a);
        RJob ra{(const float4*)part, 32, (const float4*)b_down, (float4*)out_final, 3, (const float4*)x, NI / 4};
        reduce_k<<<dim3(64, 1, 1), 256>>>(ra, ra, ra);
    }
}

// round 14
// speedup vs baseline: 1.0406x; 1.0406x over previous
#include <cuda_runtime.h>
#include <cuda_bf16.h>
#include <math.h>
#include <stdint.h>

#define NB   64
#define NI   1024
#define NHID 2048
#define NH   8
#define ND   256
#define EPS  1e-5f

// ---------------- device scratch ----------------
__device__ float g_xn[NB * NI];
__device__ float g_xl[NB * NHID];
__device__ float g_xr[NB * NHID];
__device__ float g_xc[NB * NHID];
__device__ float g_xskip[NB * NHID];
__device__ float g_o[NB * NHID];
__device__ float g_q[NB * NHID];
__device__ float g_k[NB * NHID];
__device__ float g_v[NB * NHID];
__device__ float g_outpre[NB * NHID];
__device__ float g_ig[NB * NH];
__device__ float g_fg[NB * NH];
__device__ float g_part[24 * NB * NHID];        // split-K partial slots (12.6MB)

// ---------------- helpers ----------------
__device__ __forceinline__ float blockReduce256(float v) {
    __shared__ float red[256];
    int t = threadIdx.x;
    red[t] = v;
    __syncthreads();
#pragma unroll
    for (int s = 128; s > 0; s >>= 1) {
        if (t < s) red[t] += red[t + s];
        __syncthreads();
    }
    float r = red[0];
    __syncthreads();
    return r;
}
__device__ __forceinline__ float sigmoidf_(float x) { return 1.f / (1.f + expf(-x)); }
__device__ __forceinline__ float siluf_(float x) { return x / (1.f + expf(-x)); }

__device__ __forceinline__ float ldcs(const float* p) { return __ldcs(p); }
__device__ __forceinline__ float4 ldcs4(const float* p) { return __ldcs((const float4*)p); }

// split a float pair into bf16x2 hi and lo words (low half = first element)
__device__ __forceinline__ void pack_hl(float x, float y, uint32_t& hi, uint32_t& lo) {
    __nv_bfloat162 h = __float22bfloat162_rn(make_float2(x, y));
    float2 hf = __bfloat1622float2(h);
    __nv_bfloat162 l = __float22bfloat162_rn(make_float2(x - hf.x, y - hf.y));
    hi = *(uint32_t*)&h;
    lo = *(uint32_t*)&l;
}

__device__ __forceinline__ void mma_bf16(float* acc, uint32_t a0, uint32_t a1,
                                         uint32_t a2, uint32_t a3,
                                         uint32_t b0, uint32_t b1) {
    asm volatile(
        "mma.sync.aligned.m16n8k16.row.col.f32.bf16.bf16.f32 "
        "{%0,%1,%2,%3}, {%4,%5,%6,%7}, {%8,%9}, {%0,%1,%2,%3};"
        : "+f"(acc[0]), "+f"(acc[1]), "+f"(acc[2]), "+f"(acc[3])
        : "r"(a0), "r"(a1), "r"(a2), "r"(a3), "r"(b0), "r"(b1));
}

// ---------------- LayerNorm ----------------
__global__ __launch_bounds__(256) void ln_kernel(const float* __restrict__ x,
                                                 const float* __restrict__ w,
                                                 const float* __restrict__ b) {
    int bi = blockIdx.x, t = threadIdx.x;
    const float* xr = x + bi * NI;
    float vals[4];
    float s = 0.f;
#pragma unroll
    for (int i = 0; i < 4; i++) { vals[i] = xr[t + 256 * i]; s += vals[i]; }
    float mu = blockReduce256(s) * (1.f / NI);
    float s2 = 0.f;
#pragma unroll
    for (int i = 0; i < 4; i++) { float d = vals[i] - mu; s2 += d * d; }
    float var = blockReduce256(s2) * (1.f / NI);
    float rs = rsqrtf(var + EPS);
#pragma unroll
    for (int i = 0; i < 4; i++) {
        int c = t + 256 * i;
        g_xn[bi * NI + c] = (vals[i] - mu) * rs * w[c] + b[c];
    }
}

// ---------------- tensor-core split-K GEMM: 64(M) x 128(N) tile, double-buffered ----
// wfmt=0: W fp32 [K][N]; wfmt=1: conv tap-3 — W element (k,n) at W[(n*2048+k)*4+3]
struct GJob {
    const float* A; const float* W;
    float* P;
    int K, kc, N, wfmt;
};

// dynamic smem layout (uint32 words):
//  Aph [2][16][72]  @ 0      (2304)
//  Apl [2][16][72]  @ 2304
//  Wph [2][16][136] @ 4608   (4352)
//  Wpl [2][16][136] @ 8960   ; total 13312 words = 53248 B
#define SMEM_WORDS 13312

__global__ __launch_bounds__(256, 2) void gemm_t(GJob j0, GJob j1, GJob j2) {
    GJob j = (blockIdx.z == 0) ? j0 : (blockIdx.z == 1 ? j1 : j2);
    extern __shared__ __align__(16) uint32_t sm[];
    typedef uint32_t (*A72)[72];
    typedef uint32_t (*W136)[136];

    const int tid = threadIdx.x;
    const int n0 = blockIdx.x * 128;
    const int k0 = blockIdx.y * j.kc;
    const int nst = j.kc >> 5;
    float* P = j.P + (size_t)blockIdx.y * 64 * j.N;

    const int lane = tid & 31;
    const int warp = tid >> 5;
    const int g = lane >> 2, tg = lane & 3;
    const int wm = warp & 3, wn = warp >> 2;     // 4 warps M x 2 warps N

    // A staging map: m = tid>>2, k-offset = (tid&3)*8
    const int am = tid >> 2;
    const int ak = (tid & 3) * 8;

    float4 av0, av1;
    float wv[16];
    float acc[8][4] = {};

    // ---- load stage (gmem -> regs) ----
    auto load = [&](int kb) {
        const float* Ap = j.A + (size_t)am * j.K + kb + ak;
        av0 = *(const float4*)(Ap);
        av1 = *(const float4*)(Ap + 4);
        if (j.wfmt == 0) {
#pragma unroll
            for (int r = 0; r < 2; r++) {
                int e = tid + r * 256;
                int kp = e >> 5, n4 = e & 31;
                float4 r0 = ldcs4(j.W + (size_t)(kb + 2 * kp) * j.N + n0 + n4 * 4);
                float4 r1 = ldcs4(j.W + (size_t)(kb + 2 * kp + 1) * j.N + n0 + n4 * 4);
                wv[r * 8 + 0] = r0.x; wv[r * 8 + 1] = r0.y; wv[r * 8 + 2] = r0.z; wv[r * 8 + 3] = r0.w;
                wv[r * 8 + 4] = r1.x; wv[r * 8 + 5] = r1.y; wv[r * 8 + 6] = r1.z; wv[r * 8 + 7] = r1.w;
            }
        } else {
            // coalesced-along-k: lane = k, one n row per iteration (4 lines/warp-LDG)
            const float* base = j.W + 3 + (size_t)(kb + lane) * 4;
#pragma unroll
            for (int i = 0; i < 16; i++) {
                int n = warp * 16 + i;
                wv[i] = ldcs(base + (size_t)(n0 + n) * 8192);
            }
        }
    };

    // ---- store stage (regs -> smem buffer) ----
    auto store = [&](int buf) {
        A72 aph = (A72)(sm + buf * 16 * 72);
        A72 apl = (A72)(sm + 2304 + buf * 16 * 72);
        W136 wph = (W136)(sm + 4608 + buf * 16 * 136);
        W136 wpl = (W136)(sm + 8960 + buf * 16 * 136);
        int p0 = ak >> 1;
        pack_hl(av0.x, av0.y, aph[p0 + 0][am], apl[p0 + 0][am]);
        pack_hl(av0.z, av0.w, aph[p0 + 1][am], apl[p0 + 1][am]);
        pack_hl(av1.x, av1.y, aph[p0 + 2][am], apl[p0 + 2][am]);
        pack_hl(av1.z, av1.w, aph[p0 + 3][am], apl[p0 + 3][am]);
        if (j.wfmt == 0) {
#pragma unroll
            for (int r = 0; r < 2; r++) {
                int e = tid + r * 256;
                int kp = e >> 5, n4 = e & 31;
                uint4 hi, lo;
                pack_hl(wv[r * 8 + 0], wv[r * 8 + 4], hi.x, lo.x);
                pack_hl(wv[r * 8 + 1], wv[r * 8 + 5], hi.y, lo.y);
                pack_hl(wv[r * 8 + 2], wv[r * 8 + 6], hi.z, lo.z);
                pack_hl(wv[r * 8 + 3], wv[r * 8 + 7], hi.w, lo.w);
                *(uint4*)&wph[kp][n4 * 4] = hi;
                *(uint4*)&wpl[kp][n4 * 4] = lo;
            }
        } else {
            // lane holds k = lane; even lanes pack (k, k+1) via shfl
#pragma unroll
            for (int i = 0; i < 16; i++) {
                float v = wv[i];
                float v2 = __shfl_down_sync(0xffffffffu, v, 1);
                if ((lane & 1) == 0) {
                    uint32_t hi, lo;
                    pack_hl(v, v2, hi, lo);
                    int kp = lane >> 1;           // 0..15
                    int n = warp * 16 + i;        // 0..127
                    wph[kp][n] = hi;
                    wpl[kp][n] = lo;
                }
            }
        }
    };

    // ---- compute on a smem buffer ----
    auto compute = [&](int buf) {
        A72 aph = (A72)(sm + buf * 16 * 72);
        A72 apl = (A72)(sm + 2304 + buf * 16 * 72);
        W136 wph = (W136)(sm + 4608 + buf * 16 * 136);
        W136 wpl = (W136)(sm + 8960 + buf * 16 * 136);
#pragma unroll
        for (int st = 0; st < 2; st++) {
            int kr = st * 8;
            int mrow = wm * 16 + g;
            uint32_t a0h = aph[kr + tg][mrow];
            uint32_t a1h = aph[kr + tg][mrow + 8];
            uint32_t a2h = aph[kr + tg + 4][mrow];
            uint32_t a3h = aph[kr + tg + 4][mrow + 8];
            uint32_t a0l = apl[kr + tg][mrow];
            uint32_t a1l = apl[kr + tg][mrow + 8];
            uint32_t a2l = apl[kr + tg + 4][mrow];
            uint32_t a3l = apl[kr + tg + 4][mrow + 8];
#pragma unroll
            for (int jt = 0; jt < 8; jt++) {
                int col = wn * 64 + jt * 8 + g;
                uint32_t b0h = wph[kr + tg][col];
                uint32_t b1h = wph[kr + tg + 4][col];
                uint32_t b0l = wpl[kr + tg][col];
                uint32_t b1l = wpl[kr + tg + 4][col];
                mma_bf16(acc[jt], a0h, a1h, a2h, a3h, b0h, b1h);
                mma_bf16(acc[jt], a0h, a1h, a2h, a3h, b0l, b1l);
                mma_bf16(acc[jt], a0l, a1l, a2l, a3l, b0h, b1h);
            }
        }
    };

    load(k0);
    store(0);
    __syncthreads();
    for (int s = 0; s < nst; s++) {
        if (s + 1 < nst) load(k0 + (s + 1) * 32);
        compute(s & 1);
        if (s + 1 < nst) {
            store((s + 1) & 1);
            __syncthreads();
        }
    }

    // ---- write partials ----
#pragma unroll
    for (int jt = 0; jt < 8; jt++) {
        int col = n0 + wn * 64 + jt * 8 + tg * 2;
        int row0 = wm * 16 + g;
        *(float2*)(P + (size_t)row0 * j.N + col) = make_float2(acc[jt][0], acc[jt][1]);
        *(float2*)(P + (size_t)(row0 + 8) * j.N + col) = make_float2(acc[jt][2], acc[jt][3]);
    }
}

// ---------------- float4 split-K reduce + epilogue, tri-job ----------------
struct RJob {
    const float4* P; int np;
    const float4* bias; float4* C;
    int mode; const float4* R; int N4;
};

__global__ __launch_bounds__(256) void reduce_k(RJob r0, RJob r1, RJob r2) {
    RJob r = (blockIdx.z == 0) ? r0 : (blockIdx.z == 1 ? r1 : r2);
    int idx = blockIdx.x * 256 + threadIdx.x;
    int total = 64 * r.N4;
    if (idx >= total) return;
    int n4 = idx % r.N4;
    float4 s = make_float4(0.f, 0.f, 0.f, 0.f);
#pragma unroll 8
    for (int p = 0; p < r.np; p++) {
        float4 v = r.P[(size_t)p * total + idx];
        s.x += v.x; s.y += v.y; s.z += v.z; s.w += v.w;
    }
    float4 b = r.bias[n4];
    s.x += b.x; s.y += b.y; s.z += b.z; s.w += b.w;
    if (r.mode == 1) {
        s.x = siluf_(s.x); s.y = siluf_(s.y); s.z = siluf_(s.z); s.w = siluf_(s.w);
    } else if (r.mode == 2) {
        s.x = sigmoidf_(s.x); s.y = sigmoidf_(s.y); s.z = sigmoidf_(s.z); s.w = sigmoidf_(s.w);
    } else if (r.mode == 3) {
        float4 rv = r.R[idx];
        s.x += rv.x; s.y += rv.y; s.z += rv.z; s.w += rv.w;
    }
    r.C[idx] = s;
}

// ---------------- block-diagonal q/k/v GEMMs + fused i/f gates ----------------
// grid (4, 2, 32): z<24 -> qkv (which=z>>3, h=z&7, 32x64 tile); z>=24 -> gates for
// batch b = (z-24)*8 + blockIdx.y*4 + blockIdx.x. 128 threads.
__global__ __launch_bounds__(128) void qkv_kernel(const float* __restrict__ Wq,
                                                  const float* __restrict__ Wk,
                                                  const float* __restrict__ Wv,
                                                  const float* __restrict__ bq,
                                                  const float* __restrict__ bk,
                                                  const float* __restrict__ bv,
                                                  const float* __restrict__ Wi,
                                                  const float* __restrict__ bi,
                                                  const float* __restrict__ Wf,
                                                  const float* __restrict__ bf,
                                                  const float* __restrict__ m_prev,
                                                  float* __restrict__ m_out) {
    int z = blockIdx.z;
    if (z >= 24) {
        int b = (z - 24) * 8 + blockIdx.y * 4 + blockIdx.x;
        int t = threadIdx.x;
        float pi[8] = {}, pf[8] = {};
        for (int k = t; k < NHID; k += 128) {
            float xv = g_xc[b * NHID + k];
            const float4* wi4 = (const float4*)(Wi + k * 8);
            const float4* wf4 = (const float4*)(Wf + k * 8);
            float4 a0 = wi4[0], a1 = wi4[1], f0 = wf4[0], f1 = wf4[1];
            pi[0] += xv * a0.x; pi[1] += xv * a0.y; pi[2] += xv * a0.z; pi[3] += xv * a0.w;
            pi[4] += xv * a1.x; pi[5] += xv * a1.y; pi[6] += xv * a1.z; pi[7] += xv * a1.w;
            pf[0] += xv * f0.x; pf[1] += xv * f0.y; pf[2] += xv * f0.z; pf[3] += xv * f0.w;
            pf[4] += xv * f1.x; pf[5] += xv * f1.y; pf[6] += xv * f1.z; pf[7] += xv * f1.w;
        }
        __shared__ float s[128 * 16];
#pragma unroll
        for (int h = 0; h < 8; h++) { s[t * 16 + h] = pi[h]; s[t * 16 + 8 + h] = pf[h]; }
        __syncthreads();
        if (t < 16) {
            float a = 0.f;
            for (int r = 0; r < 128; r++) a += s[r * 16 + t];
            s[t] = a;
        }
        __syncthreads();
        if (t < 8) {
            float it = s[t] + bi[t];
            float ft = s[8 + t] + bf[t];
            float mp = m_prev[b * 8 + t];
            float m = fmaxf(ft + mp, it);
            m_out[b * 8 + t] = m;
            g_ig[b * 8 + t] = expf(it - m);
            g_fg[b * 8 + t] = expf(ft + mp - m);
        }
        return;
    }
    int which = z >> 3, h = z & 7;
    const float* A = (which == 2) ? g_xl : g_xc;
    const float* W; const float* bias; float* C; float scale = 1.f;
    if (which == 0) { W = Wq; bias = bq; C = g_q; }
    else if (which == 1) { W = Wk; bias = bk; C = g_k; scale = 0.0625f; }
    else { W = Wv; bias = bv; C = g_v; }
    W += (size_t)h * ND * ND;
    bias += h * ND;
    int n0 = blockIdx.x * 64;
    int m0 = blockIdx.y * 32;
    __shared__ __align__(16) float As[32][36];
    __shared__ __align__(16) float Ws[32][68];
    int tx = threadIdx.x & 15, ty = threadIdx.x >> 4;
    float acc[4][4] = {};
    for (int kb = 0; kb < ND; kb += 32) {
#pragma unroll
        for (int r = 0; r < 2; r++) {
            int ee = threadIdx.x + r * 128;
            int k4 = ee & 7, m = ee >> 3;
            float4 v = *(const float4*)(A + (size_t)(m0 + m) * NHID + h * ND + kb + 4 * k4);
            *(float4*)&As[m][4 * k4] = v;
        }
#pragma unroll
        for (int r = 0; r < 4; r++) {
            int ee = threadIdx.x + r * 128;
            int n4 = ee & 15, k = ee >> 4;
            float4 v = *(const float4*)(W + (size_t)(kb + k) * ND + n0 + 4 * n4);
            *(float4*)&Ws[k][4 * n4] = v;
        }
        __syncthreads();
#pragma unroll
        for (int kk = 0; kk < 32; kk++) {
            float4 w = *(const float4*)&Ws[kk][tx * 4];
            float a0 = As[ty * 4 + 0][kk];
            float a1 = As[ty * 4 + 1][kk];
            float a2 = As[ty * 4 + 2][kk];
            float a3 = As[ty * 4 + 3][kk];
            acc[0][0] += a0 * w.x; acc[0][1] += a0 * w.y; acc[0][2] += a0 * w.z; acc[0][3] += a0 * w.w;
            acc[1][0] += a1 * w.x; acc[1][1] += a1 * w.y; acc[1][2] += a1 * w.z; acc[1][3] += a1 * w.w;
            acc[2][0] += a2 * w.x; acc[2][1] += a2 * w.y; acc[2][2] += a2 * w.z; acc[2][3] += a2 * w.w;
            acc[3][0] += a3 * w.x; acc[3][1] += a3 * w.y; acc[3][2] += a3 * w.z; acc[3][3] += a3 * w.w;
        }
        __syncthreads();
    }
#pragma unroll
    for (int i = 0; i < 4; i++) {
        int m = m0 + ty * 4 + i;
        int n = n0 + tx * 4;
        float4 b4 = *(const float4*)(bias + n);
        float4 v = make_float4((acc[i][0] + b4.x) * scale, (acc[i][1] + b4.y) * scale,
                               (acc[i][2] + b4.z) * scale, (acc[i][3] + b4.w) * scale);
        *(float4*)(C + (size_t)m * NHID + h * ND + n) = v;
    }
}

// ---------------- fused state update + readout + GroupNorm + gating ----------------
__global__ __launch_bounds__(256) void state_kernel(const float* __restrict__ c_prev,
                                                    const float* __restrict__ n_prev,
                                                    const float* __restrict__ gn_w,
                                                    const float* __restrict__ gn_b,
                                                    float* __restrict__ c_out,
                                                    float* __restrict__ n_out,
                                                    float* __restrict__ h_out) {
    int bh = blockIdx.x;
    int b = bh >> 3, h = bh & 7;
    int t = threadIdx.x;
    __shared__ __align__(16) float qs[256], ks[256], vs[256], hts[256];
    __shared__ float den_s;
    float fg = g_fg[bh], ig = g_ig[bh];
    int base = bh * ND;
    float qv = g_q[base + t], kv = g_k[base + t], vv = g_v[base + t];
    qs[t] = qv; ks[t] = kv; vs[t] = vv;
    float nt = fg * n_prev[base + t] + ig * kv;
    n_out[base + t] = nt;
    float den = blockReduce256(nt * qv);
    if (t == 0) den_s = fmaxf(den, 1.f);
    __syncthreads();
    den = den_s;
    int w = t >> 5, lane = t & 31;
    const float4* cp4 = (const float4*)(c_prev + (size_t)bh * ND * ND);
    float4* ct4 = (float4*)(c_out + (size_t)bh * ND * ND);
    const float4* qs4 = (const float4*)qs;
    const float4* ks4 = (const float4*)ks;
    for (int d0 = w * 32; d0 < w * 32 + 32; d0 += 4) {
        float acc0 = 0.f, acc1 = 0.f, acc2 = 0.f, acc3 = 0.f;
        float vd0 = vs[d0 + 0] * ig, vd1 = vs[d0 + 1] * ig;
        float vd2 = vs[d0 + 2] * ig, vd3 = vs[d0 + 3] * ig;
#pragma unroll
        for (int p = 0; p < 2; p++) {
            int ci = lane + p * 32;
            float4 kk = ks4[ci];
            float4 qq = qs4[ci];
            float4 cp0 = cp4[(size_t)(d0 + 0) * 64 + ci];
            float4 cp1 = cp4[(size_t)(d0 + 1) * 64 + ci];
            float4 cp2 = cp4[(size_t)(d0 + 2) * 64 + ci];
            float4 cp3 = cp4[(size_t)(d0 + 3) * 64 + ci];
            float4 c0, c1, c2, c3;
            c0.x = fg * cp0.x + vd0 * kk.x; c0.y = fg * cp0.y + vd0 * kk.y;
            c0.z = fg * cp0.z + vd0 * kk.z; c0.w = fg * cp0.w + vd0 * kk.w;
            c1.x = fg * cp1.x + vd1 * kk.x; c1.y = fg * cp1.y + vd1 * kk.y;
            c1.z = fg * cp1.z + vd1 * kk.z; c1.w = fg * cp1.w + vd1 * kk.w;
            c2.x = fg * cp2.x + vd2 * kk.x; c2.y = fg * cp2.y + vd2 * kk.y;
            c2.z = fg * cp2.z + vd2 * kk.z; c2.w = fg * cp2.w + vd2 * kk.w;
            c3.x = fg * cp3.x + vd3 * kk.x; c3.y = fg * cp3.y + vd3 * kk.y;
            c3.z = fg * cp3.z + vd3 * kk.z; c3.w = fg * cp3.w + vd3 * kk.w;
            ct4[(size_t)(d0 + 0) * 64 + ci] = c0;
            ct4[(size_t)(d0 + 1) * 64 + ci] = c1;
            ct4[(size_t)(d0 + 2) * 64 + ci] = c2;
            ct4[(size_t)(d0 + 3) * 64 + ci] = c3;
            acc0 += c0.x * qq.x + c0.y * qq.y + c0.z * qq.z + c0.w * qq.w;
            acc1 += c1.x * qq.x + c1.y * qq.y + c1.z * qq.z + c1.w * qq.w;
            acc2 += c2.x * qq.x + c2.y * qq.y + c2.z * qq.z + c2.w * qq.w;
            acc3 += c3.x * qq.x + c3.y * qq.y + c3.z * qq.z + c3.w * qq.w;
        }
#pragma unroll
        for (int off = 16; off > 0; off >>= 1) {
            acc0 += __shfl_xor_sync(0xffffffffu, acc0, off);
            acc1 += __shfl_xor_sync(0xffffffffu, acc1, off);
            acc2 += __shfl_xor_sync(0xffffffffu, acc2, off);
            acc3 += __shfl_xor_sync(0xffffffffu, acc3, off);
        }
        if (lane == 0) {
            float h0 = g_o[base + d0 + 0] * acc0 / den;
            float h1 = g_o[base + d0 + 1] * acc1 / den;
            float h2 = g_o[base + d0 + 2] * acc2 / den;
            float h3 = g_o[base + d0 + 3] * acc3 / den;
            hts[d0 + 0] = h0; hts[d0 + 1] = h1; hts[d0 + 2] = h2; hts[d0 + 3] = h3;
            h_out[base + d0 + 0] = h0; h_out[base + d0 + 1] = h1;
            h_out[base + d0 + 2] = h2; h_out[base + d0 + 3] = h3;
        }
    }
    __syncthreads();
    float hv = hts[t];
    float mu = blockReduce256(hv) * (1.f / ND);
    float dv = hv - mu;
    float var = blockReduce256(dv * dv) * (1.f / ND);
    float g = dv * rsqrtf(var + EPS);
    int hid = h * ND + t;
    float xrv = g_xr[b * NHID + hid];
    g_outpre[b * NHID + hid] =
        (g * gn_w[hid] + gn_b[hid] + g_xskip[b * NHID + hid]) * siluf_(xrv);
}

// ---------------- host launcher ----------------
extern "C" void kernel_launch(void* const* d_in, const int* in_sizes, int n_in,
                              void* d_out, int out_size) {
    (void)in_sizes; (void)n_in; (void)out_size;
    const float* x      = (const float*)d_in[0];
    const float* c_prev = (const float*)d_in[2];
    const float* n_prev = (const float*)d_in[3];
    const float* m_prev = (const float*)d_in[4];
    const float* ln_w   = (const float*)d_in[5];
    const float* ln_b   = (const float*)d_in[6];
    const float* W_ul   = (const float*)d_in[7];
    const float* b_ul   = (const float*)d_in[8];
    const float* W_ur   = (const float*)d_in[9];
    const float* b_ur   = (const float*)d_in[10];
    const float* W_conv = (const float*)d_in[11];
    const float* b_conv = (const float*)d_in[12];
    const float* W_skip = (const float*)d_in[13];
    const float* b_skip = (const float*)d_in[14];
    const float* W_q    = (const float*)d_in[15];
    const float* b_q    = (const float*)d_in[16];
    const float* W_k    = (const float*)d_in[17];
    const float* b_k    = (const float*)d_in[18];
    const float* W_v    = (const float*)d_in[19];
    const float* b_v    = (const float*)d_in[20];
    const float* W_i    = (const float*)d_in[21];
    const float* b_i    = (const float*)d_in[22];
    const float* W_f    = (const float*)d_in[23];
    const float* b_f    = (const float*)d_in[24];
    const float* W_o    = (const float*)d_in[25];
    const float* b_o    = (const float*)d_in[26];
    const float* W_down = (const float*)d_in[27];
    const float* b_down = (const float*)d_in[28];
    const float* gn_w   = (const float*)d_in[29];
    const float* gn_b   = (const float*)d_in[30];

    float* out = (float*)d_out;
    float* out_final = out;
    float* out_h = out + NB * NI;
    float* out_c = out_h + NB * NH * ND;
    float* out_n = out_c + (size_t)NB * NH * ND * ND;
    float* out_m = out_n + NB * NH * ND;

    void *p_xn, *p_xl, *p_xr, *p_xc, *p_xskip, *p_o, *p_outpre, *p_part;
    cudaGetSymbolAddress(&p_xn, g_xn);
    cudaGetSymbolAddress(&p_xl, g_xl);
    cudaGetSymbolAddress(&p_xr, g_xr);
    cudaGetSymbolAddress(&p_xc, g_xc);
    cudaGetSymbolAddress(&p_xskip, g_xskip);
    cudaGetSymbolAddress(&p_o, g_o);
    cudaGetSymbolAddress(&p_outpre, g_outpre);
    cudaGetSymbolAddress(&p_part, g_part);
    float* xn = (float*)p_xn;
    float* xl = (float*)p_xl;
    float* xr = (float*)p_xr;
    float* xc = (float*)p_xc;
    float* xskip = (float*)p_xskip;
    float* o = (float*)p_o;
    float* outpre = (float*)p_outpre;
    float* part = (float*)p_part;

    const int SLOT = NB * NHID;   // 131072 floats per [64 x 2048] partial slot
    const int SMEM_BYTES = SMEM_WORDS * 4;   // 53248
    cudaFuncSetAttribute(gemm_t, cudaFuncAttributeMaxDynamicSharedMemorySize, SMEM_BYTES);

    // 1. LayerNorm
    ln_kernel<<<NB, 256>>>(x, ln_w, ln_b);

    // 2. xl = xn@W_ul : K=1024, 8-way split
    {
        GJob a{xn, W_ul, part, NI, 128, NHID, 0};
        gemm_t<<<dim3(16, 8, 1), 256, SMEM_BYTES>>>(a, a, a);
        RJob ra{(const float4*)part, 8, (const float4*)b_ul, (float4*)xl, 0, nullptr, NHID / 4};
        reduce_k<<<dim3(128, 1, 1), 256>>>(ra, ra, ra);
    }

    // 3. conv (tap-3) + o-pre + ur, one z=3 launch; then tri-reduce
    {
        GJob a{xl, W_conv, part, NHID, 256, NHID, 1};                      // slots 0-7
        GJob b2{xl, W_o, part + (size_t)8 * SLOT, NHID, 256, NHID, 0};     // slots 8-15
        GJob c3{xn, W_ur, part + (size_t)16 * SLOT, NI, 128, NHID, 0};     // slots 16-23
        gemm_t<<<dim3(16, 8, 3), 256, SMEM_BYTES>>>(a, b2, c3);
        RJob ra{(const float4*)part, 8, (const float4*)b_conv, (float4*)xc, 1, nullptr, NHID / 4};
        RJob rb{(const float4*)(part + (size_t)8 * SLOT), 8, (const float4*)b_o, (float4*)o, 2, nullptr, NHID / 4};
        RJob rc{(const float4*)(part + (size_t)16 * SLOT), 8, (const float4*)b_ur, (float4*)xr, 0, nullptr, NHID / 4};
        reduce_k<<<dim3(128, 1, 3), 256>>>(ra, rb, rc);
    }

    // 4. skip GEMM (16-way split) + qkv(+gates) ; then reduce xskip
    {
        GJob a{xc, W_skip, part, NHID, 128, NHID, 0};
        gemm_t<<<dim3(16, 16, 1), 256, SMEM_BYTES>>>(a, a, a);
        qkv_kernel<<<dim3(4, 2, 32), 128>>>(W_q, W_k, W_v, b_q, b_k, b_v,
                                            W_i, b_i, W_f, b_f, m_prev, out_m);
        RJob ra{(const float4*)part, 16, (const float4*)b_skip, (float4*)xskip, 0, nullptr, NHID / 4};
        reduce_k<<<dim3(128, 1, 1), 256>>>(ra, ra, ra);
    }

    // 5. fused state update / readout / groupnorm / gating
    state_kernel<<<NB * NH, 256>>>(c_prev, n_prev, gn_w, gn_b, out_c, out_n, out_h);

    // 6. final = outpre @ W_down + b_down + x : K=2048, 32-way split, N=1024
    {
        GJob a{outpre, W_down, part, NHID, 64, NI, 0};
        gemm_t<<<dim3(8, 32, 1), 256, SMEM_BYTES>>>(a, a, a);
        RJob ra{(const float4*)part, 32, (const float4*)b_down, (float4*)out_final, 3, (const float4*)x, NI / 4};
        reduce_k<<<dim3(64, 1, 1), 256>>>(ra, ra, ra);
    }
}

// round 15
// speedup vs baseline: 1.0586x; 1.0172x over previous
#include <cuda_runtime.h>
#include <cuda_bf16.h>
#include <math.h>
#include <stdint.h>

#define NB   64
#define NI   1024
#define NHID 2048
#define NH   8
#define ND   256
#define EPS  1e-5f

// ---------------- device scratch ----------------
__device__ float g_xn[NB * NI];
__device__ float g_xl[NB * NHID];
__device__ float g_xr[NB * NHID];
__device__ float g_xc[NB * NHID];
__device__ float g_xskip[NB * NHID];
__device__ float g_o[NB * NHID];
__device__ float g_q[NB * NHID];
__device__ float g_k[NB * NHID];
__device__ float g_v[NB * NHID];
__device__ float g_outpre[NB * NHID];
__device__ float g_ig[NB * NH];
__device__ float g_fg[NB * NH];
__device__ float g_part[32 * NB * NHID];        // split-K partial slots (16.8MB)

// ---------------- helpers ----------------
__device__ __forceinline__ float blockReduce256(float v) {
    __shared__ float red[256];
    int t = threadIdx.x;
    red[t] = v;
    __syncthreads();
#pragma unroll
    for (int s = 128; s > 0; s >>= 1) {
        if (t < s) red[t] += red[t + s];
        __syncthreads();
    }
    float r = red[0];
    __syncthreads();
    return r;
}
__device__ __forceinline__ float sigmoidf_(float x) { return 1.f / (1.f + expf(-x)); }
__device__ __forceinline__ float siluf_(float x) { return x / (1.f + expf(-x)); }

// split a float pair into bf16x2 hi and lo words (low half = first element)
__device__ __forceinline__ void pack_hl(float x, float y, uint32_t& hi, uint32_t& lo) {
    __nv_bfloat162 h = __float22bfloat162_rn(make_float2(x, y));
    float2 hf = __bfloat1622float2(h);
    __nv_bfloat162 l = __float22bfloat162_rn(make_float2(x - hf.x, y - hf.y));
    hi = *(uint32_t*)&h;
    lo = *(uint32_t*)&l;
}

__device__ __forceinline__ void mma_bf16(float* acc, uint32_t a0, uint32_t a1,
                                         uint32_t a2, uint32_t a3,
                                         uint32_t b0, uint32_t b1) {
    asm volatile(
        "mma.sync.aligned.m16n8k16.row.col.f32.bf16.bf16.f32 "
        "{%0,%1,%2,%3}, {%4,%5,%6,%7}, {%8,%9}, {%0,%1,%2,%3};"
        : "+f"(acc[0]), "+f"(acc[1]), "+f"(acc[2]), "+f"(acc[3])
        : "r"(a0), "r"(a1), "r"(a2), "r"(a3), "r"(b0), "r"(b1));
}

// ---------------- LayerNorm ----------------
__global__ __launch_bounds__(256) void ln_kernel(const float* __restrict__ x,
                                                 const float* __restrict__ w,
                                                 const float* __restrict__ b) {
    int bi = blockIdx.x, t = threadIdx.x;
    const float* xr = x + bi * NI;
    float vals[4];
    float s = 0.f;
#pragma unroll
    for (int i = 0; i < 4; i++) { vals[i] = xr[t + 256 * i]; s += vals[i]; }
    float mu = blockReduce256(s) * (1.f / NI);
    float s2 = 0.f;
#pragma unroll
    for (int i = 0; i < 4; i++) { float d = vals[i] - mu; s2 += d * d; }
    float var = blockReduce256(s2) * (1.f / NI);
    float rs = rsqrtf(var + EPS);
#pragma unroll
    for (int i = 0; i < 4; i++) {
        int c = t + 256 * i;
        g_xn[bi * NI + c] = (vals[i] - mu) * rs * w[c] + b[c];
    }
}

// ---------------- tensor-core split-K GEMM: 64(M) x 128(N) tile, double-buffered ----
// wfmt=0: W fp32 [K][N]; wfmt=1: conv tap-3 — W element (k,n) at W[(n*2048+k)*4+3]
struct GJob {
    const float* A; const float* W;
    float* P;
    int K, kc, N, wfmt;
};

// dynamic smem layout (uint32 words):
//  Aph [2][16][72]  @ 0      (2304)
//  Apl [2][16][72]  @ 2304
//  Wph [2][16][136] @ 4608   (4352)
//  Wpl [2][16][136] @ 8960   ; total 13312 words = 53248 B
#define SMEM_WORDS 13312

__global__ __launch_bounds__(256, 2) void gemm_t(GJob j0, GJob j1, GJob j2) {
    GJob j = (blockIdx.z == 0) ? j0 : (blockIdx.z == 1 ? j1 : j2);
    extern __shared__ __align__(16) uint32_t sm[];
    typedef uint32_t (*A72)[72];
    typedef uint32_t (*W136)[136];

    const int tid = threadIdx.x;
    const int n0 = blockIdx.x * 128;
    const int k0 = blockIdx.y * j.kc;
    const int nst = j.kc >> 5;
    float* P = j.P + (size_t)blockIdx.y * 64 * j.N;

    const int lane = tid & 31;
    const int warp = tid >> 5;
    const int g = lane >> 2, tg = lane & 3;
    const int wm = warp & 3, wn = warp >> 2;     // 4 warps M x 2 warps N

    // A staging map: m = tid>>2, k-offset = (tid&3)*8
    const int am = tid >> 2;
    const int ak = (tid & 3) * 8;

    float4 av0, av1;
    float wv[16];
    float acc[8][4] = {};

    // ---- load stage (gmem -> regs) ----
    auto load = [&](int kb) {
        const float* Ap = j.A + (size_t)am * j.K + kb + ak;
        av0 = *(const float4*)(Ap);
        av1 = *(const float4*)(Ap + 4);
        if (j.wfmt == 0) {
#pragma unroll
            for (int r = 0; r < 2; r++) {
                int e = tid + r * 256;
                int kp = e >> 5, n4 = e & 31;
                float4 r0 = *(const float4*)(j.W + (size_t)(kb + 2 * kp) * j.N + n0 + n4 * 4);
                float4 r1 = *(const float4*)(j.W + (size_t)(kb + 2 * kp + 1) * j.N + n0 + n4 * 4);
                wv[r * 8 + 0] = r0.x; wv[r * 8 + 1] = r0.y; wv[r * 8 + 2] = r0.z; wv[r * 8 + 3] = r0.w;
                wv[r * 8 + 4] = r1.x; wv[r * 8 + 5] = r1.y; wv[r * 8 + 6] = r1.z; wv[r * 8 + 7] = r1.w;
            }
        } else {
            // coalesced-along-k: lane = k, one n row per iteration (4 lines/warp-LDG)
            const float* base = j.W + 3 + (size_t)(kb + lane) * 4;
#pragma unroll
            for (int i = 0; i < 16; i++) {
                int n = warp * 16 + i;
                wv[i] = base[(size_t)(n0 + n) * 8192];
            }
        }
    };

    // ---- store stage (regs -> smem buffer) ----
    auto store = [&](int buf) {
        A72 aph = (A72)(sm + buf * 16 * 72);
        A72 apl = (A72)(sm + 2304 + buf * 16 * 72);
        W136 wph = (W136)(sm + 4608 + buf * 16 * 136);
        W136 wpl = (W136)(sm + 8960 + buf * 16 * 136);
        int p0 = ak >> 1;
        pack_hl(av0.x, av0.y, aph[p0 + 0][am], apl[p0 + 0][am]);
        pack_hl(av0.z, av0.w, aph[p0 + 1][am], apl[p0 + 1][am]);
        pack_hl(av1.x, av1.y, aph[p0 + 2][am], apl[p0 + 2][am]);
        pack_hl(av1.z, av1.w, aph[p0 + 3][am], apl[p0 + 3][am]);
        if (j.wfmt == 0) {
#pragma unroll
            for (int r = 0; r < 2; r++) {
                int e = tid + r * 256;
                int kp = e >> 5, n4 = e & 31;
                uint4 hi, lo;
                pack_hl(wv[r * 8 + 0], wv[r * 8 + 4], hi.x, lo.x);
                pack_hl(wv[r * 8 + 1], wv[r * 8 + 5], hi.y, lo.y);
                pack_hl(wv[r * 8 + 2], wv[r * 8 + 6], hi.z, lo.z);
                pack_hl(wv[r * 8 + 3], wv[r * 8 + 7], hi.w, lo.w);
                *(uint4*)&wph[kp][n4 * 4] = hi;
                *(uint4*)&wpl[kp][n4 * 4] = lo;
            }
        } else {
            // lane holds k = lane; even lanes pack (k, k+1) via shfl
#pragma unroll
            for (int i = 0; i < 16; i++) {
                float v = wv[i];
                float v2 = __shfl_down_sync(0xffffffffu, v, 1);
                if ((lane & 1) == 0) {
                    uint32_t hi, lo;
                    pack_hl(v, v2, hi, lo);
                    int kp = lane >> 1;           // 0..15
                    int n = warp * 16 + i;        // 0..127
                    wph[kp][n] = hi;
                    wpl[kp][n] = lo;
                }
            }
        }
    };

    // ---- compute on a smem buffer ----
    auto compute = [&](int buf) {
        A72 aph = (A72)(sm + buf * 16 * 72);
        A72 apl = (A72)(sm + 2304 + buf * 16 * 72);
        W136 wph = (W136)(sm + 4608 + buf * 16 * 136);
        W136 wpl = (W136)(sm + 8960 + buf * 16 * 136);
#pragma unroll
        for (int st = 0; st < 2; st++) {
            int kr = st * 8;
            int mrow = wm * 16 + g;
            uint32_t a0h = aph[kr + tg][mrow];
            uint32_t a1h = aph[kr + tg][mrow + 8];
            uint32_t a2h = aph[kr + tg + 4][mrow];
            uint32_t a3h = aph[kr + tg + 4][mrow + 8];
            uint32_t a0l = apl[kr + tg][mrow];
            uint32_t a1l = apl[kr + tg][mrow + 8];
            uint32_t a2l = apl[kr + tg + 4][mrow];
            uint32_t a3l = apl[kr + tg + 4][mrow + 8];
#pragma unroll
            for (int jt = 0; jt < 8; jt++) {
                int col = wn * 64 + jt * 8 + g;
                uint32_t b0h = wph[kr + tg][col];
                uint32_t b1h = wph[kr + tg + 4][col];
                uint32_t b0l = wpl[kr + tg][col];
                uint32_t b1l = wpl[kr + tg + 4][col];
                mma_bf16(acc[jt], a0h, a1h, a2h, a3h, b0h, b1h);
                mma_bf16(acc[jt], a0h, a1h, a2h, a3h, b0l, b1l);
                mma_bf16(acc[jt], a0l, a1l, a2l, a3l, b0h, b1h);
            }
        }
    };

    load(k0);
    store(0);
    __syncthreads();
    for (int s = 0; s < nst; s++) {
        if (s + 1 < nst) load(k0 + (s + 1) * 32);
        compute(s & 1);
        if (s + 1 < nst) {
            store((s + 1) & 1);
            __syncthreads();
        }
    }

    // ---- write partials ----
#pragma unroll
    for (int jt = 0; jt < 8; jt++) {
        int col = n0 + wn * 64 + jt * 8 + tg * 2;
        int row0 = wm * 16 + g;
        *(float2*)(P + (size_t)row0 * j.N + col) = make_float2(acc[jt][0], acc[jt][1]);
        *(float2*)(P + (size_t)(row0 + 8) * j.N + col) = make_float2(acc[jt][2], acc[jt][3]);
    }
}

// ---------------- float4 split-K reduce + epilogue, tri-job ----------------
struct RJob {
    const float4* P; int np;
    const float4* bias; float4* C;
    int mode; const float4* R; int N4;
};

__global__ __launch_bounds__(256) void reduce_k(RJob r0, RJob r1, RJob r2) {
    RJob r = (blockIdx.z == 0) ? r0 : (blockIdx.z == 1 ? r1 : r2);
    int idx = blockIdx.x * 256 + threadIdx.x;
    int total = 64 * r.N4;
    if (idx >= total) return;
    int n4 = idx % r.N4;
    float4 s = make_float4(0.f, 0.f, 0.f, 0.f);
#pragma unroll 8
    for (int p = 0; p < r.np; p++) {
        float4 v = r.P[(size_t)p * total + idx];
        s.x += v.x; s.y += v.y; s.z += v.z; s.w += v.w;
    }
    float4 b = r.bias[n4];
    s.x += b.x; s.y += b.y; s.z += b.z; s.w += b.w;
    if (r.mode == 1) {
        s.x = siluf_(s.x); s.y = siluf_(s.y); s.z = siluf_(s.z); s.w = siluf_(s.w);
    } else if (r.mode == 2) {
        s.x = sigmoidf_(s.x); s.y = sigmoidf_(s.y); s.z = sigmoidf_(s.z); s.w = sigmoidf_(s.w);
    } else if (r.mode == 3) {
        float4 rv = r.R[idx];
        s.x += rv.x; s.y += rv.y; s.z += rv.z; s.w += rv.w;
    }
    r.C[idx] = s;
}

// ---------------- block-diagonal q/k/v GEMMs + fused i/f gates ----------------
// grid (4, 2, 32): z<24 -> qkv (which=z>>3, h=z&7, 32x64 tile); z>=24 -> gates for
// batch b = (z-24)*8 + blockIdx.y*4 + blockIdx.x. 128 threads.
__global__ __launch_bounds__(128) void qkv_kernel(const float* __restrict__ Wq,
                                                  const float* __restrict__ Wk,
                                                  const float* __restrict__ Wv,
                                                  const float* __restrict__ bq,
                                                  const float* __restrict__ bk,
                                                  const float* __restrict__ bv,
                                                  const float* __restrict__ Wi,
                                                  const float* __restrict__ bi,
                                                  const float* __restrict__ Wf,
                                                  const float* __restrict__ bf,
                                                  const float* __restrict__ m_prev,
                                                  float* __restrict__ m_out) {
    int z = blockIdx.z;
    if (z >= 24) {
        int b = (z - 24) * 8 + blockIdx.y * 4 + blockIdx.x;
        int t = threadIdx.x;
        float pi[8] = {}, pf[8] = {};
        for (int k = t; k < NHID; k += 128) {
            float xv = g_xc[b * NHID + k];
            const float4* wi4 = (const float4*)(Wi + k * 8);
            const float4* wf4 = (const float4*)(Wf + k * 8);
            float4 a0 = wi4[0], a1 = wi4[1], f0 = wf4[0], f1 = wf4[1];
            pi[0] += xv * a0.x; pi[1] += xv * a0.y; pi[2] += xv * a0.z; pi[3] += xv * a0.w;
            pi[4] += xv * a1.x; pi[5] += xv * a1.y; pi[6] += xv * a1.z; pi[7] += xv * a1.w;
            pf[0] += xv * f0.x; pf[1] += xv * f0.y; pf[2] += xv * f0.z; pf[3] += xv * f0.w;
            pf[4] += xv * f1.x; pf[5] += xv * f1.y; pf[6] += xv * f1.z; pf[7] += xv * f1.w;
        }
        __shared__ float s[128 * 16];
#pragma unroll
        for (int h = 0; h < 8; h++) { s[t * 16 + h] = pi[h]; s[t * 16 + 8 + h] = pf[h]; }
        __syncthreads();
        if (t < 16) {
            float a = 0.f;
            for (int r = 0; r < 128; r++) a += s[r * 16 + t];
            s[t] = a;
        }
        __syncthreads();
        if (t < 8) {
            float it = s[t] + bi[t];
            float ft = s[8 + t] + bf[t];
            float mp = m_prev[b * 8 + t];
            float m = fmaxf(ft + mp, it);
            m_out[b * 8 + t] = m;
            g_ig[b * 8 + t] = expf(it - m);
            g_fg[b * 8 + t] = expf(ft + mp - m);
        }
        return;
    }
    int which = z >> 3, h = z & 7;
    const float* A = (which == 2) ? g_xl : g_xc;
    const float* W; const float* bias; float* C; float scale = 1.f;
    if (which == 0) { W = Wq; bias = bq; C = g_q; }
    else if (which == 1) { W = Wk; bias = bk; C = g_k; scale = 0.0625f; }
    else { W = Wv; bias = bv; C = g_v; }
    W += (size_t)h * ND * ND;
    bias += h * ND;
    int n0 = blockIdx.x * 64;
    int m0 = blockIdx.y * 32;
    __shared__ __align__(16) float As[32][36];
    __shared__ __align__(16) float Ws[32][68];
    int tx = threadIdx.x & 15, ty = threadIdx.x >> 4;
    float acc[4][4] = {};
    for (int kb = 0; kb < ND; kb += 32) {
#pragma unroll
        for (int r = 0; r < 2; r++) {
            int ee = threadIdx.x + r * 128;
            int k4 = ee & 7, m = ee >> 3;
            float4 v = *(const float4*)(A + (size_t)(m0 + m) * NHID + h * ND + kb + 4 * k4);
            *(float4*)&As[m][4 * k4] = v;
        }
#pragma unroll
        for (int r = 0; r < 4; r++) {
            int ee = threadIdx.x + r * 128;
            int n4 = ee & 15, k = ee >> 4;
            float4 v = *(const float4*)(W + (size_t)(kb + k) * ND + n0 + 4 * n4);
            *(float4*)&Ws[k][4 * n4] = v;
        }
        __syncthreads();
#pragma unroll
        for (int kk = 0; kk < 32; kk++) {
            float4 w = *(const float4*)&Ws[kk][tx * 4];
            float a0 = As[ty * 4 + 0][kk];
            float a1 = As[ty * 4 + 1][kk];
            float a2 = As[ty * 4 + 2][kk];
            float a3 = As[ty * 4 + 3][kk];
            acc[0][0] += a0 * w.x; acc[0][1] += a0 * w.y; acc[0][2] += a0 * w.z; acc[0][3] += a0 * w.w;
            acc[1][0] += a1 * w.x; acc[1][1] += a1 * w.y; acc[1][2] += a1 * w.z; acc[1][3] += a1 * w.w;
            acc[2][0] += a2 * w.x; acc[2][1] += a2 * w.y; acc[2][2] += a2 * w.z; acc[2][3] += a2 * w.w;
            acc[3][0] += a3 * w.x; acc[3][1] += a3 * w.y; acc[3][2] += a3 * w.z; acc[3][3] += a3 * w.w;
        }
        __syncthreads();
    }
#pragma unroll
    for (int i = 0; i < 4; i++) {
        int m = m0 + ty * 4 + i;
        int n = n0 + tx * 4;
        float4 b4 = *(const float4*)(bias + n);
        float4 v = make_float4((acc[i][0] + b4.x) * scale, (acc[i][1] + b4.y) * scale,
                               (acc[i][2] + b4.z) * scale, (acc[i][3] + b4.w) * scale);
        *(float4*)(C + (size_t)m * NHID + h * ND + n) = v;
    }
}

// ---------------- fused state update + readout + GroupNorm + gating ----------------
__global__ __launch_bounds__(256) void state_kernel(const float* __restrict__ c_prev,
                                                    const float* __restrict__ n_prev,
                                                    const float* __restrict__ gn_w,
                                                    const float* __restrict__ gn_b,
                                                    float* __restrict__ c_out,
                                                    float* __restrict__ n_out,
                                                    float* __restrict__ h_out) {
    int bh = blockIdx.x;
    int b = bh >> 3, h = bh & 7;
    int t = threadIdx.x;
    __shared__ __align__(16) float qs[256], ks[256], vs[256], hts[256];
    __shared__ float den_s;
    float fg = g_fg[bh], ig = g_ig[bh];
    int base = bh * ND;
    float qv = g_q[base + t], kv = g_k[base + t], vv = g_v[base + t];
    qs[t] = qv; ks[t] = kv; vs[t] = vv;
    float nt = fg * n_prev[base + t] + ig * kv;
    n_out[base + t] = nt;
    float den = blockReduce256(nt * qv);
    if (t == 0) den_s = fmaxf(den, 1.f);
    __syncthreads();
    den = den_s;
    int w = t >> 5, lane = t & 31;
    const float4* cp4 = (const float4*)(c_prev + (size_t)bh * ND * ND);
    float4* ct4 = (float4*)(c_out + (size_t)bh * ND * ND);
    const float4* qs4 = (const float4*)qs;
    const float4* ks4 = (const float4*)ks;
    for (int d0 = w * 32; d0 < w * 32 + 32; d0 += 4) {
        float acc0 = 0.f, acc1 = 0.f, acc2 = 0.f, acc3 = 0.f;
        float vd0 = vs[d0 + 0] * ig, vd1 = vs[d0 + 1] * ig;
        float vd2 = vs[d0 + 2] * ig, vd3 = vs[d0 + 3] * ig;
#pragma unroll
        for (int p = 0; p < 2; p++) {
            int ci = lane + p * 32;
            float4 kk = ks4[ci];
            float4 qq = qs4[ci];
            float4 cp0 = cp4[(size_t)(d0 + 0) * 64 + ci];
            float4 cp1 = cp4[(size_t)(d0 + 1) * 64 + ci];
            float4 cp2 = cp4[(size_t)(d0 + 2) * 64 + ci];
            float4 cp3 = cp4[(size_t)(d0 + 3) * 64 + ci];
            float4 c0, c1, c2, c3;
            c0.x = fg * cp0.x + vd0 * kk.x; c0.y = fg * cp0.y + vd0 * kk.y;
            c0.z = fg * cp0.z + vd0 * kk.z; c0.w = fg * cp0.w + vd0 * kk.w;
            c1.x = fg * cp1.x + vd1 * kk.x; c1.y = fg * cp1.y + vd1 * kk.y;
            c1.z = fg * cp1.z + vd1 * kk.z; c1.w = fg * cp1.w + vd1 * kk.w;
            c2.x = fg * cp2.x + vd2 * kk.x; c2.y = fg * cp2.y + vd2 * kk.y;
            c2.z = fg * cp2.z + vd2 * kk.z; c2.w = fg * cp2.w + vd2 * kk.w;
            c3.x = fg * cp3.x + vd3 * kk.x; c3.y = fg * cp3.y + vd3 * kk.y;
            c3.z = fg * cp3.z + vd3 * kk.z; c3.w = fg * cp3.w + vd3 * kk.w;
            ct4[(size_t)(d0 + 0) * 64 + ci] = c0;
            ct4[(size_t)(d0 + 1) * 64 + ci] = c1;
            ct4[(size_t)(d0 + 2) * 64 + ci] = c2;
            ct4[(size_t)(d0 + 3) * 64 + ci] = c3;
            acc0 += c0.x * qq.x + c0.y * qq.y + c0.z * qq.z + c0.w * qq.w;
            acc1 += c1.x * qq.x + c1.y * qq.y + c1.z * qq.z + c1.w * qq.w;
            acc2 += c2.x * qq.x + c2.y * qq.y + c2.z * qq.z + c2.w * qq.w;
            acc3 += c3.x * qq.x + c3.y * qq.y + c3.z * qq.z + c3.w * qq.w;
        }
#pragma unroll
        for (int off = 16; off > 0; off >>= 1) {
            acc0 += __shfl_xor_sync(0xffffffffu, acc0, off);
            acc1 += __shfl_xor_sync(0xffffffffu, acc1, off);
            acc2 += __shfl_xor_sync(0xffffffffu, acc2, off);
            acc3 += __shfl_xor_sync(0xffffffffu, acc3, off);
        }
        if (lane == 0) {
            float h0 = g_o[base + d0 + 0] * acc0 / den;
            float h1 = g_o[base + d0 + 1] * acc1 / den;
            float h2 = g_o[base + d0 + 2] * acc2 / den;
            float h3 = g_o[base + d0 + 3] * acc3 / den;
            hts[d0 + 0] = h0; hts[d0 + 1] = h1; hts[d0 + 2] = h2; hts[d0 + 3] = h3;
            h_out[base + d0 + 0] = h0; h_out[base + d0 + 1] = h1;
            h_out[base + d0 + 2] = h2; h_out[base + d0 + 3] = h3;
        }
    }
    __syncthreads();
    float hv = hts[t];
    float mu = blockReduce256(hv) * (1.f / ND);
    float dv = hv - mu;
    float var = blockReduce256(dv * dv) * (1.f / ND);
    float g = dv * rsqrtf(var + EPS);
    int hid = h * ND + t;
    float xrv = g_xr[b * NHID + hid];
    g_outpre[b * NHID + hid] =
        (g * gn_w[hid] + gn_b[hid] + g_xskip[b * NHID + hid]) * siluf_(xrv);
}

// ---------------- host launcher ----------------
extern "C" void kernel_launch(void* const* d_in, const int* in_sizes, int n_in,
                              void* d_out, int out_size) {
    (void)in_sizes; (void)n_in; (void)out_size;
    const float* x      = (const float*)d_in[0];
    const float* c_prev = (const float*)d_in[2];
    const float* n_prev = (const float*)d_in[3];
    const float* m_prev = (const float*)d_in[4];
    const float* ln_w   = (const float*)d_in[5];
    const float* ln_b   = (const float*)d_in[6];
    const float* W_ul   = (const float*)d_in[7];
    const float* b_ul   = (const float*)d_in[8];
    const float* W_ur   = (const float*)d_in[9];
    const float* b_ur   = (const float*)d_in[10];
    const float* W_conv = (const float*)d_in[11];
    const float* b_conv = (const float*)d_in[12];
    const float* W_skip = (const float*)d_in[13];
    const float* b_skip = (const float*)d_in[14];
    const float* W_q    = (const float*)d_in[15];
    const float* b_q    = (const float*)d_in[16];
    const float* W_k    = (const float*)d_in[17];
    const float* b_k    = (const float*)d_in[18];
    const float* W_v    = (const float*)d_in[19];
    const float* b_v    = (const float*)d_in[20];
    const float* W_i    = (const float*)d_in[21];
    const float* b_i    = (const float*)d_in[22];
    const float* W_f    = (const float*)d_in[23];
    const float* b_f    = (const float*)d_in[24];
    const float* W_o    = (const float*)d_in[25];
    const float* b_o    = (const float*)d_in[26];
    const float* W_down = (const float*)d_in[27];
    const float* b_down = (const float*)d_in[28];
    const float* gn_w   = (const float*)d_in[29];
    const float* gn_b   = (const float*)d_in[30];

    float* out = (float*)d_out;
    float* out_final = out;
    float* out_h = out + NB * NI;
    float* out_c = out_h + NB * NH * ND;
    float* out_n = out_c + (size_t)NB * NH * ND * ND;
    float* out_m = out_n + NB * NH * ND;

    void *p_xn, *p_xl, *p_xr, *p_xc, *p_xskip, *p_o, *p_outpre, *p_part;
    cudaGetSymbolAddress(&p_xn, g_xn);
    cudaGetSymbolAddress(&p_xl, g_xl);
    cudaGetSymbolAddress(&p_xr, g_xr);
    cudaGetSymbolAddress(&p_xc, g_xc);
    cudaGetSymbolAddress(&p_xskip, g_xskip);
    cudaGetSymbolAddress(&p_o, g_o);
    cudaGetSymbolAddress(&p_outpre, g_outpre);
    cudaGetSymbolAddress(&p_part, g_part);
    float* xn = (float*)p_xn;
    float* xl = (float*)p_xl;
    float* xr = (float*)p_xr;
    float* xc = (float*)p_xc;
    float* xskip = (float*)p_xskip;
    float* o = (float*)p_o;
    float* outpre = (float*)p_outpre;
    float* part = (float*)p_part;

    const int SLOT = NB * NHID;   // 131072 floats per [64 x 2048] partial slot
    const int SMEM_BYTES = SMEM_WORDS * 4;   // 53248
    cudaFuncSetAttribute(gemm_t, cudaFuncAttributeMaxDynamicSharedMemorySize, SMEM_BYTES);

    // 1. LayerNorm
    ln_kernel<<<NB, 256>>>(x, ln_w, ln_b);

    // 2. xl = xn@W_ul : K=1024, 16-way split (256 blocks = 1 full wave)
    {
        GJob a{xn, W_ul, part, NI, 64, NHID, 0};
        gemm_t<<<dim3(16, 16, 1), 256, SMEM_BYTES>>>(a, a, a);
        RJob ra{(const float4*)part, 16, (const float4*)b_ul, (float4*)xl, 0, nullptr, NHID / 4};
        reduce_k<<<dim3(128, 1, 1), 256>>>(ra, ra, ra);
    }

    // 3a. conv (tap-3) ALONE: 16-way split, 256 blocks = full wave of conv streams
    {
        GJob a{xl, W_conv, part, NHID, 128, NHID, 1};                      // slots 0-15
        gemm_t<<<dim3(16, 16, 1), 256, SMEM_BYTES>>>(a, a, a);
    }
    // 3b. o-pre + ur dual launch (dense float4 streams), then tri-reduce
    {
        GJob b2{xl, W_o, part + (size_t)16 * SLOT, NHID, 256, NHID, 0};    // slots 16-23
        GJob c3{xn, W_ur, part + (size_t)24 * SLOT, NI, 128, NHID, 0};     // slots 24-31
        gemm_t<<<dim3(16, 8, 2), 256, SMEM_BYTES>>>(b2, c3, c3);
        RJob ra{(const float4*)part, 16, (const float4*)b_conv, (float4*)xc, 1, nullptr, NHID / 4};
        RJob rb{(const float4*)(part + (size_t)16 * SLOT), 8, (const float4*)b_o, (float4*)o, 2, nullptr, NHID / 4};
        RJob rc{(const float4*)(part + (size_t)24 * SLOT), 8, (const float4*)b_ur, (float4*)xr, 0, nullptr, NHID / 4};
        reduce_k<<<dim3(128, 1, 3), 256>>>(ra, rb, rc);
    }

    // 4. skip GEMM (16-way split) + qkv(+gates) ; then reduce xskip
    {
        GJob a{xc, W_skip, part, NHID, 128, NHID, 0};
        gemm_t<<<dim3(16, 16, 1), 256, SMEM_BYTES>>>(a, a, a);
        qkv_kernel<<<dim3(4, 2, 32), 128>>>(W_q, W_k, W_v, b_q, b_k, b_v,
                                            W_i, b_i, W_f, b_f, m_prev, out_m);
        RJob ra{(const float4*)part, 16, (const float4*)b_skip, (float4*)xskip, 0, nullptr, NHID / 4};
        reduce_k<<<dim3(128, 1, 1), 256>>>(ra, ra, ra);
    }

    // 5. fused state update / readout / groupnorm / gating
    state_kernel<<<NB * NH, 256>>>(c_prev, n_prev, gn_w, gn_b, out_c, out_n, out_h);

    // 6. final = outpre @ W_down + b_down + x : K=2048, 32-way split, N=1024
    {
        GJob a{outpre, W_down, part, NHID, 64, NI, 0};
        gemm_t<<<dim3(8, 32, 1), 256, SMEM_BYTES>>>(a, a, a);
        RJob ra{(const float4*)part, 32, (const float4*)b_down, (float4*)out_final, 3, (const float4*)x, NI / 4};
        reduce_k<<<dim3(64, 1, 1), 256>>>(ra, ra, ra);
    }
}

// round 16
// speedup vs baseline: 1.0875x; 1.0274x over previous
#include <cuda_runtime.h>
#include <cuda_bf16.h>
#include <math.h>
#include <stdint.h>

#define NB   64
#define NI   1024
#define NHID 2048
#define NH   8
#define ND   256
#define EPS  1e-5f

// ---------------- device scratch ----------------
__device__ float g_xn[NB * NI];
__device__ float g_xl[NB * NHID];
__device__ float g_xr[NB * NHID];
__device__ float g_xc[NB * NHID];
__device__ float g_xskip[NB * NHID];
__device__ float g_o[NB * NHID];
__device__ float g_q[NB * NHID];
__device__ float g_k[NB * NHID];
__device__ float g_v[NB * NHID];
__device__ float g_outpre[NB * NHID];
__device__ float g_ig[NB * NH];
__device__ float g_fg[NB * NH];
__device__ float g_part[32 * NB * NHID];        // split-K partial slots (16.8MB)

// ---------------- helpers ----------------
__device__ __forceinline__ float blockReduce256(float v) {
    __shared__ float red[256];
    int t = threadIdx.x;
    red[t] = v;
    __syncthreads();
#pragma unroll
    for (int s = 128; s > 0; s >>= 1) {
        if (t < s) red[t] += red[t + s];
        __syncthreads();
    }
    float r = red[0];
    __syncthreads();
    return r;
}
__device__ __forceinline__ float sigmoidf_(float x) { return 1.f / (1.f + expf(-x)); }
__device__ __forceinline__ float siluf_(float x) { return x / (1.f + expf(-x)); }

// split a float pair into bf16x2 hi and lo words (low half = first element)
__device__ __forceinline__ void pack_hl(float x, float y, uint32_t& hi, uint32_t& lo) {
    __nv_bfloat162 h = __float22bfloat162_rn(make_float2(x, y));
    float2 hf = __bfloat1622float2(h);
    __nv_bfloat162 l = __float22bfloat162_rn(make_float2(x - hf.x, y - hf.y));
    hi = *(uint32_t*)&h;
    lo = *(uint32_t*)&l;
}

__device__ __forceinline__ void mma_bf16(float* acc, uint32_t a0, uint32_t a1,
                                         uint32_t a2, uint32_t a3,
                                         uint32_t b0, uint32_t b1) {
    asm volatile(
        "mma.sync.aligned.m16n8k16.row.col.f32.bf16.bf16.f32 "
        "{%0,%1,%2,%3}, {%4,%5,%6,%7}, {%8,%9}, {%0,%1,%2,%3};"
        : "+f"(acc[0]), "+f"(acc[1]), "+f"(acc[2]), "+f"(acc[3])
        : "r"(a0), "r"(a1), "r"(a2), "r"(a3), "r"(b0), "r"(b1));
}

// ---------------- LayerNorm ----------------
__global__ __launch_bounds__(256) void ln_kernel(const float* __restrict__ x,
                                                 const float* __restrict__ w,
                                                 const float* __restrict__ b) {
    int bi = blockIdx.x, t = threadIdx.x;
    const float* xr = x + bi * NI;
    float vals[4];
    float s = 0.f;
#pragma unroll
    for (int i = 0; i < 4; i++) { vals[i] = xr[t + 256 * i]; s += vals[i]; }
    float mu = blockReduce256(s) * (1.f / NI);
    float s2 = 0.f;
#pragma unroll
    for (int i = 0; i < 4; i++) { float d = vals[i] - mu; s2 += d * d; }
    float var = blockReduce256(s2) * (1.f / NI);
    float rs = rsqrtf(var + EPS);
#pragma unroll
    for (int i = 0; i < 4; i++) {
        int c = t + 256 * i;
        g_xn[bi * NI + c] = (vals[i] - mu) * rs * w[c] + b[c];
    }
}

// ---------------- tensor-core split-K GEMM: 64(M) x 128(N) tile, double-buffered ----
// wfmt=0: W fp32 [K][N]; wfmt=1: conv tap-3 — W element (k,n) at W[(n*2048+k)*4+3]
struct GJob {
    const float* A; const float* W;
    float* P;
    int K, kc, N, wfmt;
};

// dynamic smem layout (uint32 words):
//  Aph [2][16][72]  @ 0      (2304)
//  Apl [2][16][72]  @ 2304
//  Wph [2][16][136] @ 4608   (4352)
//  Wpl [2][16][136] @ 8960   ; total 13312 words = 53248 B
#define SMEM_WORDS 13312

__global__ __launch_bounds__(256, 2) void gemm_t(GJob j0, GJob j1, GJob j2) {
    GJob j = (blockIdx.z == 0) ? j0 : (blockIdx.z == 1 ? j1 : j2);
    extern __shared__ __align__(16) uint32_t sm[];
    typedef uint32_t (*A72)[72];
    typedef uint32_t (*W136)[136];

    const int tid = threadIdx.x;
    const int n0 = blockIdx.x * 128;
    const int k0 = blockIdx.y * j.kc;
    const int nst = j.kc >> 5;
    float* P = j.P + (size_t)blockIdx.y * 64 * j.N;

    const int lane = tid & 31;
    const int warp = tid >> 5;
    const int g = lane >> 2, tg = lane & 3;
    const int wm = warp & 3, wn = warp >> 2;     // 4 warps M x 2 warps N

    // A staging map: m = tid>>2, k-offset = (tid&3)*8
    const int am = tid >> 2;
    const int ak = (tid & 3) * 8;

    float4 av0, av1;
    float wv[16];
    float acc[8][4] = {};

    // ---- load stage (gmem -> regs) ----
    auto load = [&](int kb) {
        const float* Ap = j.A + (size_t)am * j.K + kb + ak;
        av0 = *(const float4*)(Ap);
        av1 = *(const float4*)(Ap + 4);
        if (j.wfmt == 0) {
#pragma unroll
            for (int r = 0; r < 2; r++) {
                int e = tid + r * 256;
                int kp = e >> 5, n4 = e & 31;
                float4 r0 = *(const float4*)(j.W + (size_t)(kb + 2 * kp) * j.N + n0 + n4 * 4);
                float4 r1 = *(const float4*)(j.W + (size_t)(kb + 2 * kp + 1) * j.N + n0 + n4 * 4);
                wv[r * 8 + 0] = r0.x; wv[r * 8 + 1] = r0.y; wv[r * 8 + 2] = r0.z; wv[r * 8 + 3] = r0.w;
                wv[r * 8 + 4] = r1.x; wv[r * 8 + 5] = r1.y; wv[r * 8 + 6] = r1.z; wv[r * 8 + 7] = r1.w;
            }
        } else {
            // coalesced-along-k: lane = k, one n row per iteration (4 lines/warp-LDG)
            const float* base = j.W + 3 + (size_t)(kb + lane) * 4;
#pragma unroll
            for (int i = 0; i < 16; i++) {
                int n = warp * 16 + i;
                wv[i] = base[(size_t)(n0 + n) * 8192];
            }
        }
    };

    // ---- store stage (regs -> smem buffer) ----
    auto store = [&](int buf) {
        A72 aph = (A72)(sm + buf * 16 * 72);
        A72 apl = (A72)(sm + 2304 + buf * 16 * 72);
        W136 wph = (W136)(sm + 4608 + buf * 16 * 136);
        W136 wpl = (W136)(sm + 8960 + buf * 16 * 136);
        int p0 = ak >> 1;
        pack_hl(av0.x, av0.y, aph[p0 + 0][am], apl[p0 + 0][am]);
        pack_hl(av0.z, av0.w, aph[p0 + 1][am], apl[p0 + 1][am]);
        pack_hl(av1.x, av1.y, aph[p0 + 2][am], apl[p0 + 2][am]);
        pack_hl(av1.z, av1.w, aph[p0 + 3][am], apl[p0 + 3][am]);
        if (j.wfmt == 0) {
#pragma unroll
            for (int r = 0; r < 2; r++) {
                int e = tid + r * 256;
                int kp = e >> 5, n4 = e & 31;
                uint4 hi, lo;
                pack_hl(wv[r * 8 + 0], wv[r * 8 + 4], hi.x, lo.x);
                pack_hl(wv[r * 8 + 1], wv[r * 8 + 5], hi.y, lo.y);
                pack_hl(wv[r * 8 + 2], wv[r * 8 + 6], hi.z, lo.z);
                pack_hl(wv[r * 8 + 3], wv[r * 8 + 7], hi.w, lo.w);
                *(uint4*)&wph[kp][n4 * 4] = hi;
                *(uint4*)&wpl[kp][n4 * 4] = lo;
            }
        } else {
            // lane holds k = lane; even lanes pack (k, k+1) via shfl
#pragma unroll
            for (int i = 0; i < 16; i++) {
                float v = wv[i];
                float v2 = __shfl_down_sync(0xffffffffu, v, 1);
                if ((lane & 1) == 0) {
                    uint32_t hi, lo;
                    pack_hl(v, v2, hi, lo);
                    int kp = lane >> 1;           // 0..15
                    int n = warp * 16 + i;        // 0..127
                    wph[kp][n] = hi;
                    wpl[kp][n] = lo;
                }
            }
        }
    };

    // ---- compute on a smem buffer ----
    auto compute = [&](int buf) {
        A72 aph = (A72)(sm + buf * 16 * 72);
        A72 apl = (A72)(sm + 2304 + buf * 16 * 72);
        W136 wph = (W136)(sm + 4608 + buf * 16 * 136);
        W136 wpl = (W136)(sm + 8960 + buf * 16 * 136);
#pragma unroll
        for (int st = 0; st < 2; st++) {
            int kr = st * 8;
            int mrow = wm * 16 + g;
            uint32_t a0h = aph[kr + tg][mrow];
            uint32_t a1h = aph[kr + tg][mrow + 8];
            uint32_t a2h = aph[kr + tg + 4][mrow];
            uint32_t a3h = aph[kr + tg + 4][mrow + 8];
            uint32_t a0l = apl[kr + tg][mrow];
            uint32_t a1l = apl[kr + tg][mrow + 8];
            uint32_t a2l = apl[kr + tg + 4][mrow];
            uint32_t a3l = apl[kr + tg + 4][mrow + 8];
#pragma unroll
            for (int jt = 0; jt < 8; jt++) {
                int col = wn * 64 + jt * 8 + g;
                uint32_t b0h = wph[kr + tg][col];
                uint32_t b1h = wph[kr + tg + 4][col];
                uint32_t b0l = wpl[kr + tg][col];
                uint32_t b1l = wpl[kr + tg + 4][col];
                mma_bf16(acc[jt], a0h, a1h, a2h, a3h, b0h, b1h);
                mma_bf16(acc[jt], a0h, a1h, a2h, a3h, b0l, b1l);
                mma_bf16(acc[jt], a0l, a1l, a2l, a3l, b0h, b1h);
            }
        }
    };

    load(k0);
    store(0);
    __syncthreads();
    for (int s = 0; s < nst; s++) {
        if (s + 1 < nst) load(k0 + (s + 1) * 32);
        compute(s & 1);
        if (s + 1 < nst) {
            store((s + 1) & 1);
            __syncthreads();
        }
    }

    // ---- write partials ----
#pragma unroll
    for (int jt = 0; jt < 8; jt++) {
        int col = n0 + wn * 64 + jt * 8 + tg * 2;
        int row0 = wm * 16 + g;
        *(float2*)(P + (size_t)row0 * j.N + col) = make_float2(acc[jt][0], acc[jt][1]);
        *(float2*)(P + (size_t)(row0 + 8) * j.N + col) = make_float2(acc[jt][2], acc[jt][3]);
    }
}

// ---------------- float4 split-K reduce + epilogue, tri-job ----------------
struct RJob {
    const float4* P; int np;
    const float4* bias; float4* C;
    int mode; const float4* R; int N4;
};

__global__ __launch_bounds__(256) void reduce_k(RJob r0, RJob r1, RJob r2) {
    RJob r = (blockIdx.z == 0) ? r0 : (blockIdx.z == 1 ? r1 : r2);
    int idx = blockIdx.x * 256 + threadIdx.x;
    int total = 64 * r.N4;
    if (idx >= total) return;
    int n4 = idx % r.N4;
    float4 s = make_float4(0.f, 0.f, 0.f, 0.f);
#pragma unroll 8
    for (int p = 0; p < r.np; p++) {
        float4 v = r.P[(size_t)p * total + idx];
        s.x += v.x; s.y += v.y; s.z += v.z; s.w += v.w;
    }
    float4 b = r.bias[n4];
    s.x += b.x; s.y += b.y; s.z += b.z; s.w += b.w;
    if (r.mode == 1) {
        s.x = siluf_(s.x); s.y = siluf_(s.y); s.z = siluf_(s.z); s.w = siluf_(s.w);
    } else if (r.mode == 2) {
        s.x = sigmoidf_(s.x); s.y = sigmoidf_(s.y); s.z = sigmoidf_(s.z); s.w = sigmoidf_(s.w);
    } else if (r.mode == 3) {
        float4 rv = r.R[idx];
        s.x += rv.x; s.y += rv.y; s.z += rv.z; s.w += rv.w;
    }
    r.C[idx] = s;
}

// ---------------- block-diagonal q/k/v GEMMs + fused i/f gates ----------------
// grid (4, 2, 32): z<24 -> qkv (which=z>>3, h=z&7, 32x64 tile); z>=24 -> gates for
// batch b = (z-24)*8 + blockIdx.y*4 + blockIdx.x. 128 threads.
__global__ __launch_bounds__(128) void qkv_kernel(const float* __restrict__ Wq,
                                                  const float* __restrict__ Wk,
                                                  const float* __restrict__ Wv,
                                                  const float* __restrict__ bq,
                                                  const float* __restrict__ bk,
                                                  const float* __restrict__ bv,
                                                  const float* __restrict__ Wi,
                                                  const float* __restrict__ bi,
                                                  const float* __restrict__ Wf,
                                                  const float* __restrict__ bf,
                                                  const float* __restrict__ m_prev,
                                                  float* __restrict__ m_out) {
    int z = blockIdx.z;
    if (z >= 24) {
        int b = (z - 24) * 8 + blockIdx.y * 4 + blockIdx.x;
        int t = threadIdx.x;
        float pi[8] = {}, pf[8] = {};
        for (int k = t; k < NHID; k += 128) {
            float xv = g_xc[b * NHID + k];
            const float4* wi4 = (const float4*)(Wi + k * 8);
            const float4* wf4 = (const float4*)(Wf + k * 8);
            float4 a0 = wi4[0], a1 = wi4[1], f0 = wf4[0], f1 = wf4[1];
            pi[0] += xv * a0.x; pi[1] += xv * a0.y; pi[2] += xv * a0.z; pi[3] += xv * a0.w;
            pi[4] += xv * a1.x; pi[5] += xv * a1.y; pi[6] += xv * a1.z; pi[7] += xv * a1.w;
            pf[0] += xv * f0.x; pf[1] += xv * f0.y; pf[2] += xv * f0.z; pf[3] += xv * f0.w;
            pf[4] += xv * f1.x; pf[5] += xv * f1.y; pf[6] += xv * f1.z; pf[7] += xv * f1.w;
        }
        __shared__ float s[128 * 16];
#pragma unroll
        for (int h = 0; h < 8; h++) { s[t * 16 + h] = pi[h]; s[t * 16 + 8 + h] = pf[h]; }
        __syncthreads();
        if (t < 16) {
            float a = 0.f;
            for (int r = 0; r < 128; r++) a += s[r * 16 + t];
            s[t] = a;
        }
        __syncthreads();
        if (t < 8) {
            float it = s[t] + bi[t];
            float ft = s[8 + t] + bf[t];
            float mp = m_prev[b * 8 + t];
            float m = fmaxf(ft + mp, it);
            m_out[b * 8 + t] = m;
            g_ig[b * 8 + t] = expf(it - m);
            g_fg[b * 8 + t] = expf(ft + mp - m);
        }
        return;
    }
    int which = z >> 3, h = z & 7;
    const float* A = (which == 2) ? g_xl : g_xc;
    const float* W; const float* bias; float* C; float scale = 1.f;
    if (which == 0) { W = Wq; bias = bq; C = g_q; }
    else if (which == 1) { W = Wk; bias = bk; C = g_k; scale = 0.0625f; }
    else { W = Wv; bias = bv; C = g_v; }
    W += (size_t)h * ND * ND;
    bias += h * ND;
    int n0 = blockIdx.x * 64;
    int m0 = blockIdx.y * 32;
    __shared__ __align__(16) float As[32][36];
    __shared__ __align__(16) float Ws[32][68];
    int tx = threadIdx.x & 15, ty = threadIdx.x >> 4;
    float acc[4][4] = {};
    for (int kb = 0; kb < ND; kb += 32) {
#pragma unroll
        for (int r = 0; r < 2; r++) {
            int ee = threadIdx.x + r * 128;
            int k4 = ee & 7, m = ee >> 3;
            float4 v = *(const float4*)(A + (size_t)(m0 + m) * NHID + h * ND + kb + 4 * k4);
            *(float4*)&As[m][4 * k4] = v;
        }
#pragma unroll
        for (int r = 0; r < 4; r++) {
            int ee = threadIdx.x + r * 128;
            int n4 = ee & 15, k = ee >> 4;
            float4 v = *(const float4*)(W + (size_t)(kb + k) * ND + n0 + 4 * n4);
            *(float4*)&Ws[k][4 * n4] = v;
        }
        __syncthreads();
#pragma unroll
        for (int kk = 0; kk < 32; kk++) {
            float4 w = *(const float4*)&Ws[kk][tx * 4];
            float a0 = As[ty * 4 + 0][kk];
            float a1 = As[ty * 4 + 1][kk];
            float a2 = As[ty * 4 + 2][kk];
            float a3 = As[ty * 4 + 3][kk];
            acc[0][0] += a0 * w.x; acc[0][1] += a0 * w.y; acc[0][2] += a0 * w.z; acc[0][3] += a0 * w.w;
            acc[1][0] += a1 * w.x; acc[1][1] += a1 * w.y; acc[1][2] += a1 * w.z; acc[1][3] += a1 * w.w;
            acc[2][0] += a2 * w.x; acc[2][1] += a2 * w.y; acc[2][2] += a2 * w.z; acc[2][3] += a2 * w.w;
            acc[3][0] += a3 * w.x; acc[3][1] += a3 * w.y; acc[3][2] += a3 * w.z; acc[3][3] += a3 * w.w;
        }
        __syncthreads();
    }
#pragma unroll
    for (int i = 0; i < 4; i++) {
        int m = m0 + ty * 4 + i;
        int n = n0 + tx * 4;
        float4 b4 = *(const float4*)(bias + n);
        float4 v = make_float4((acc[i][0] + b4.x) * scale, (acc[i][1] + b4.y) * scale,
                               (acc[i][2] + b4.z) * scale, (acc[i][3] + b4.w) * scale);
        *(float4*)(C + (size_t)m * NHID + h * ND + n) = v;
    }
}

// ---------------- fused state update + readout + GroupNorm + gating ----------------
__global__ __launch_bounds__(256) void state_kernel(const float* __restrict__ c_prev,
                                                    const float* __restrict__ n_prev,
                                                    const float* __restrict__ gn_w,
                                                    const float* __restrict__ gn_b,
                                                    float* __restrict__ c_out,
                                                    float* __restrict__ n_out,
                                                    float* __restrict__ h_out) {
    int bh = blockIdx.x;
    int b = bh >> 3, h = bh & 7;
    int t = threadIdx.x;
    __shared__ __align__(16) float qs[256], ks[256], vs[256], hts[256];
    __shared__ float den_s;
    float fg = g_fg[bh], ig = g_ig[bh];
    int base = bh * ND;
    float qv = g_q[base + t], kv = g_k[base + t], vv = g_v[base + t];
    qs[t] = qv; ks[t] = kv; vs[t] = vv;
    float nt = fg * n_prev[base + t] + ig * kv;
    n_out[base + t] = nt;
    float den = blockReduce256(nt * qv);
    if (t == 0) den_s = fmaxf(den, 1.f);
    __syncthreads();
    den = den_s;
    int w = t >> 5, lane = t & 31;
    const float4* cp4 = (const float4*)(c_prev + (size_t)bh * ND * ND);
    float4* ct4 = (float4*)(c_out + (size_t)bh * ND * ND);
    const float4* qs4 = (const float4*)qs;
    const float4* ks4 = (const float4*)ks;
    for (int d0 = w * 32; d0 < w * 32 + 32; d0 += 4) {
        float acc0 = 0.f, acc1 = 0.f, acc2 = 0.f, acc3 = 0.f;
        float vd0 = vs[d0 + 0] * ig, vd1 = vs[d0 + 1] * ig;
        float vd2 = vs[d0 + 2] * ig, vd3 = vs[d0 + 3] * ig;
#pragma unroll
        for (int p = 0; p < 2; p++) {
            int ci = lane + p * 32;
            float4 kk = ks4[ci];
            float4 qq = qs4[ci];
            float4 cp0 = cp4[(size_t)(d0 + 0) * 64 + ci];
            float4 cp1 = cp4[(size_t)(d0 + 1) * 64 + ci];
            float4 cp2 = cp4[(size_t)(d0 + 2) * 64 + ci];
            float4 cp3 = cp4[(size_t)(d0 + 3) * 64 + ci];
            float4 c0, c1, c2, c3;
            c0.x = fg * cp0.x + vd0 * kk.x; c0.y = fg * cp0.y + vd0 * kk.y;
            c0.z = fg * cp0.z + vd0 * kk.z; c0.w = fg * cp0.w + vd0 * kk.w;
            c1.x = fg * cp1.x + vd1 * kk.x; c1.y = fg * cp1.y + vd1 * kk.y;
            c1.z = fg * cp1.z + vd1 * kk.z; c1.w = fg * cp1.w + vd1 * kk.w;
            c2.x = fg * cp2.x + vd2 * kk.x; c2.y = fg * cp2.y + vd2 * kk.y;
            c2.z = fg * cp2.z + vd2 * kk.z; c2.w = fg * cp2.w + vd2 * kk.w;
            c3.x = fg * cp3.x + vd3 * kk.x; c3.y = fg * cp3.y + vd3 * kk.y;
            c3.z = fg * cp3.z + vd3 * kk.z; c3.w = fg * cp3.w + vd3 * kk.w;
            ct4[(size_t)(d0 + 0) * 64 + ci] = c0;
            ct4[(size_t)(d0 + 1) * 64 + ci] = c1;
            ct4[(size_t)(d0 + 2) * 64 + ci] = c2;
            ct4[(size_t)(d0 + 3) * 64 + ci] = c3;
            acc0 += c0.x * qq.x + c0.y * qq.y + c0.z * qq.z + c0.w * qq.w;
            acc1 += c1.x * qq.x + c1.y * qq.y + c1.z * qq.z + c1.w * qq.w;
            acc2 += c2.x * qq.x + c2.y * qq.y + c2.z * qq.z + c2.w * qq.w;
            acc3 += c3.x * qq.x + c3.y * qq.y + c3.z * qq.z + c3.w * qq.w;
        }
#pragma unroll
        for (int off = 16; off > 0; off >>= 1) {
            acc0 += __shfl_xor_sync(0xffffffffu, acc0, off);
            acc1 += __shfl_xor_sync(0xffffffffu, acc1, off);
            acc2 += __shfl_xor_sync(0xffffffffu, acc2, off);
            acc3 += __shfl_xor_sync(0xffffffffu, acc3, off);
        }
        if (lane == 0) {
            float h0 = g_o[base + d0 + 0] * acc0 / den;
            float h1 = g_o[base + d0 + 1] * acc1 / den;
            float h2 = g_o[base + d0 + 2] * acc2 / den;
            float h3 = g_o[base + d0 + 3] * acc3 / den;
            hts[d0 + 0] = h0; hts[d0 + 1] = h1; hts[d0 + 2] = h2; hts[d0 + 3] = h3;
            h_out[base + d0 + 0] = h0; h_out[base + d0 + 1] = h1;
            h_out[base + d0 + 2] = h2; h_out[base + d0 + 3] = h3;
        }
    }
    __syncthreads();
    float hv = hts[t];
    float mu = blockReduce256(hv) * (1.f / ND);
    float dv = hv - mu;
    float var = blockReduce256(dv * dv) * (1.f / ND);
    float g = dv * rsqrtf(var + EPS);
    int hid = h * ND + t;
    float xrv = g_xr[b * NHID + hid];
    g_outpre[b * NHID + hid] =
        (g * gn_w[hid] + gn_b[hid] + g_xskip[b * NHID + hid]) * siluf_(xrv);
}

// ---------------- host launcher ----------------
extern "C" void kernel_launch(void* const* d_in, const int* in_sizes, int n_in,
                              void* d_out, int out_size) {
    (void)in_sizes; (void)n_in; (void)out_size;
    const float* x      = (const float*)d_in[0];
    const float* c_prev = (const float*)d_in[2];
    const float* n_prev = (const float*)d_in[3];
    const float* m_prev = (const float*)d_in[4];
    const float* ln_w   = (const float*)d_in[5];
    const float* ln_b   = (const float*)d_in[6];
    const float* W_ul   = (const float*)d_in[7];
    const float* b_ul   = (const float*)d_in[8];
    const float* W_ur   = (const float*)d_in[9];
    const float* b_ur   = (const float*)d_in[10];
    const float* W_conv = (const float*)d_in[11];
    const float* b_conv = (const float*)d_in[12];
    const float* W_skip = (const float*)d_in[13];
    const float* b_skip = (const float*)d_in[14];
    const float* W_q    = (const float*)d_in[15];
    const float* b_q    = (const float*)d_in[16];
    const float* W_k    = (const float*)d_in[17];
    const float* b_k    = (const float*)d_in[18];
    const float* W_v    = (const float*)d_in[19];
    const float* b_v    = (const float*)d_in[20];
    const float* W_i    = (const float*)d_in[21];
    const float* b_i    = (const float*)d_in[22];
    const float* W_f    = (const float*)d_in[23];
    const float* b_f    = (const float*)d_in[24];
    const float* W_o    = (const float*)d_in[25];
    const float* b_o    = (const float*)d_in[26];
    const float* W_down = (const float*)d_in[27];
    const float* b_down = (const float*)d_in[28];
    const float* gn_w   = (const float*)d_in[29];
    const float* gn_b   = (const float*)d_in[30];

    float* out = (float*)d_out;
    float* out_final = out;
    float* out_h = out + NB * NI;
    float* out_c = out_h + NB * NH * ND;
    float* out_n = out_c + (size_t)NB * NH * ND * ND;
    float* out_m = out_n + NB * NH * ND;

    void *p_xn, *p_xl, *p_xr, *p_xc, *p_xskip, *p_o, *p_outpre, *p_part;
    cudaGetSymbolAddress(&p_xn, g_xn);
    cudaGetSymbolAddress(&p_xl, g_xl);
    cudaGetSymbolAddress(&p_xr, g_xr);
    cudaGetSymbolAddress(&p_xc, g_xc);
    cudaGetSymbolAddress(&p_xskip, g_xskip);
    cudaGetSymbolAddress(&p_o, g_o);
    cudaGetSymbolAddress(&p_outpre, g_outpre);
    cudaGetSymbolAddress(&p_part, g_part);
    float* xn = (float*)p_xn;
    float* xl = (float*)p_xl;
    float* xr = (float*)p_xr;
    float* xc = (float*)p_xc;
    float* xskip = (float*)p_xskip;
    float* o = (float*)p_o;
    float* outpre = (float*)p_outpre;
    float* part = (float*)p_part;

    const int SLOT = NB * NHID;   // 131072 floats per [64 x 2048] partial slot
    const int SMEM_BYTES = SMEM_WORDS * 4;   // 53248
    cudaFuncSetAttribute(gemm_t, cudaFuncAttributeMaxDynamicSharedMemorySize, SMEM_BYTES);

    // 1. LayerNorm
    ln_kernel<<<NB, 256>>>(x, ln_w, ln_b);

    // 2. ul + ur dual (8-way each, 256 blocks = 1 wave), dual reduce
    {
        GJob a{xn, W_ul, part, NI, 128, NHID, 0};                          // slots 0-7
        GJob b2{xn, W_ur, part + (size_t)8 * SLOT, NI, 128, NHID, 0};      // slots 8-15
        gemm_t<<<dim3(16, 8, 2), 256, SMEM_BYTES>>>(a, b2, b2);
        RJob ra{(const float4*)part, 8, (const float4*)b_ul, (float4*)xl, 0, nullptr, NHID / 4};
        RJob rb{(const float4*)(part + (size_t)8 * SLOT), 8, (const float4*)b_ur, (float4*)xr, 0, nullptr, NHID / 4};
        reduce_k<<<dim3(128, 1, 2), 256>>>(ra, rb, rb);
    }

    // 3. conv (tap-3) ALONE: 16-way split, 256 blocks = full dedicated wave
    {
        GJob a{xl, W_conv, part, NHID, 128, NHID, 1};                      // slots 0-15
        gemm_t<<<dim3(16, 16, 1), 256, SMEM_BYTES>>>(a, a, a);
        RJob ra{(const float4*)part, 16, (const float4*)b_conv, (float4*)xc, 1, nullptr, NHID / 4};
        reduce_k<<<dim3(128, 1, 1), 256>>>(ra, ra, ra);
    }

    // 4. skip + o dual (8-way each, 256 blocks) + qkv(+gates), dual reduce
    {
        GJob a{xc, W_skip, part, NHID, 256, NHID, 0};                      // slots 0-7
        GJob b2{xl, W_o, part + (size_t)8 * SLOT, NHID, 256, NHID, 0};     // slots 8-15
        gemm_t<<<dim3(16, 8, 2), 256, SMEM_BYTES>>>(a, b2, b2);
        qkv_kernel<<<dim3(4, 2, 32), 128>>>(W_q, W_k, W_v, b_q, b_k, b_v,
                                            W_i, b_i, W_f, b_f, m_prev, out_m);
        RJob ra{(const float4*)part, 8, (const float4*)b_skip, (float4*)xskip, 0, nullptr, NHID / 4};
        RJob rb{(const float4*)(part + (size_t)8 * SLOT), 8, (const float4*)b_o, (float4*)o, 2, nullptr, NHID / 4};
        reduce_k<<<dim3(128, 1, 2), 256>>>(ra, rb, rb);
    }

    // 5. fused state update / readout / groupnorm / gating
    state_kernel<<<NB * NH, 256>>>(c_prev, n_prev, gn_w, gn_b, out_c, out_n, out_h);

    // 6. final = outpre @ W_down + b_down + x : K=2048, 32-way split, N=1024
    {
        GJob a{outpre, W_down, part, NHID, 64, NI, 0};
        gemm_t<<<dim3(8, 32, 1), 256, SMEM_BYTES>>>(a, a, a);
        RJob ra{(const float4*)part, 32, (const float4*)b_down, (float4*)out_final, 3, (const float4*)x, NI / 4};
        reduce_k<<<dim3(64, 1, 1), 256>>>(ra, ra, ra);
    }
}

// round 17
// speedup vs baseline: 1.1606x; 1.0672x over previous
#include <cuda_runtime.h>
#include <cuda_bf16.h>
#include <math.h>
#include <stdint.h>

#define NB   64
#define NI   1024
#define NHID 2048
#define NH   8
#define ND   256
#define EPS  1e-5f

// ---------------- device scratch ----------------
__device__ float g_xn[NB * NI];
__device__ float g_xl[NB * NHID];
__device__ float g_xr[NB * NHID];
__device__ float g_xc[NB * NHID];
__device__ float g_xskip[NB * NHID];
__device__ float g_o[NB * NHID];
__device__ float g_q[NB * NHID];
__device__ float g_k[NB * NHID];
__device__ float g_v[NB * NHID];
__device__ float g_outpre[NB * NHID];
__device__ float g_ig[NB * NH];
__device__ float g_fg[NB * NH];
__device__ float g_part[32 * NB * NHID];        // split-K partial slots (16.8MB)

// ---------------- helpers ----------------
__device__ __forceinline__ float blockReduce256(float v) {
    __shared__ float red[256];
    int t = threadIdx.x;
    red[t] = v;
    __syncthreads();
#pragma unroll
    for (int s = 128; s > 0; s >>= 1) {
        if (t < s) red[t] += red[t + s];
        __syncthreads();
    }
    float r = red[0];
    __syncthreads();
    return r;
}
__device__ __forceinline__ float sigmoidf_(float x) { return 1.f / (1.f + expf(-x)); }
__device__ __forceinline__ float siluf_(float x) { return x / (1.f + expf(-x)); }

// split a float pair into bf16x2 hi and lo words (low half = first element)
__device__ __forceinline__ void pack_hl(float x, float y, uint32_t& hi, uint32_t& lo) {
    __nv_bfloat162 h = __float22bfloat162_rn(make_float2(x, y));
    float2 hf = __bfloat1622float2(h);
    __nv_bfloat162 l = __float22bfloat162_rn(make_float2(x - hf.x, y - hf.y));
    hi = *(uint32_t*)&h;
    lo = *(uint32_t*)&l;
}

__device__ __forceinline__ void mma_bf16(float* acc, uint32_t a0, uint32_t a1,
                                         uint32_t a2, uint32_t a3,
                                         uint32_t b0, uint32_t b1) {
    asm volatile(
        "mma.sync.aligned.m16n8k16.row.col.f32.bf16.bf16.f32 "
        "{%0,%1,%2,%3}, {%4,%5,%6,%7}, {%8,%9}, {%0,%1,%2,%3};"
        : "+f"(acc[0]), "+f"(acc[1]), "+f"(acc[2]), "+f"(acc[3])
        : "r"(a0), "r"(a1), "r"(a2), "r"(a3), "r"(b0), "r"(b1));
}

// ---------------- LayerNorm ----------------
__global__ __launch_bounds__(256) void ln_kernel(const float* __restrict__ x,
                                                 const float* __restrict__ w,
                                                 const float* __restrict__ b) {
    int bi = blockIdx.x, t = threadIdx.x;
    const float* xr = x + bi * NI;
    float vals[4];
    float s = 0.f;
#pragma unroll
    for (int i = 0; i < 4; i++) { vals[i] = xr[t + 256 * i]; s += vals[i]; }
    float mu = blockReduce256(s) * (1.f / NI);
    float s2 = 0.f;
#pragma unroll
    for (int i = 0; i < 4; i++) { float d = vals[i] - mu; s2 += d * d; }
    float var = blockReduce256(s2) * (1.f / NI);
    float rs = rsqrtf(var + EPS);
#pragma unroll
    for (int i = 0; i < 4; i++) {
        int c = t + 256 * i;
        g_xn[bi * NI + c] = (vals[i] - mu) * rs * w[c] + b[c];
    }
}

// ---------------- tensor-core split-K GEMM: 64(M) x 128(N) tile, double-buffered ----
// wfmt=0: W fp32 [K][N]; wfmt=1: conv tap-3 — W element (k,n) at W[(n*2048+k)*4+3]
struct GJob {
    const float* A; const float* W;
    float* P;
    int K, kc, N, wfmt;
};

// dynamic smem layout (uint32 words):
//  Aph [2][16][72]  @ 0      (2304)
//  Apl [2][16][72]  @ 2304
//  Wph [2][16][136] @ 4608   (4352)
//  Wpl [2][16][136] @ 8960   ; total 13312 words = 53248 B
#define SMEM_WORDS 13312

__global__ __launch_bounds__(256, 2) void gemm_t(GJob j0, GJob j1, GJob j2) {
    GJob j = (blockIdx.z == 0) ? j0 : (blockIdx.z == 1 ? j1 : j2);
    extern __shared__ __align__(16) uint32_t sm[];
    typedef uint32_t (*A72)[72];
    typedef uint32_t (*W136)[136];

    const int tid = threadIdx.x;
    const int n0 = blockIdx.x * 128;
    const int k0 = blockIdx.y * j.kc;
    const int nst = j.kc >> 5;
    float* P = j.P + (size_t)blockIdx.y * 64 * j.N;

    const int lane = tid & 31;
    const int warp = tid >> 5;
    const int g = lane >> 2, tg = lane & 3;
    const int wm = warp & 3, wn = warp >> 2;     // 4 warps M x 2 warps N

    // A staging map: m = tid>>2, k-offset = (tid&3)*8
    const int am = tid >> 2;
    const int ak = (tid & 3) * 8;

    float4 av0, av1;
    float wv[16];
    float acc[8][4] = {};

    // ---- load stage (gmem -> regs) ----
    auto load = [&](int kb) {
        const float* Ap = j.A + (size_t)am * j.K + kb + ak;
        av0 = *(const float4*)(Ap);
        av1 = *(const float4*)(Ap + 4);
        if (j.wfmt == 0) {
#pragma unroll
            for (int r = 0; r < 2; r++) {
                int e = tid + r * 256;
                int kp = e >> 5, n4 = e & 31;
                float4 r0 = *(const float4*)(j.W + (size_t)(kb + 2 * kp) * j.N + n0 + n4 * 4);
                float4 r1 = *(const float4*)(j.W + (size_t)(kb + 2 * kp + 1) * j.N + n0 + n4 * 4);
                wv[r * 8 + 0] = r0.x; wv[r * 8 + 1] = r0.y; wv[r * 8 + 2] = r0.z; wv[r * 8 + 3] = r0.w;
                wv[r * 8 + 4] = r1.x; wv[r * 8 + 5] = r1.y; wv[r * 8 + 6] = r1.z; wv[r * 8 + 7] = r1.w;
            }
        } else {
            // coalesced-along-k: lane = k, one n row per iteration (4 lines/warp-LDG)
            const float* base = j.W + 3 + (size_t)(kb + lane) * 4;
#pragma unroll
            for (int i = 0; i < 16; i++) {
                int n = warp * 16 + i;
                wv[i] = base[(size_t)(n0 + n) * 8192];
            }
        }
    };

    // ---- store stage (regs -> smem buffer) ----
    auto store = [&](int buf) {
        A72 aph = (A72)(sm + buf * 16 * 72);
        A72 apl = (A72)(sm + 2304 + buf * 16 * 72);
        W136 wph = (W136)(sm + 4608 + buf * 16 * 136);
        W136 wpl = (W136)(sm + 8960 + buf * 16 * 136);
        int p0 = ak >> 1;
        pack_hl(av0.x, av0.y, aph[p0 + 0][am], apl[p0 + 0][am]);
        pack_hl(av0.z, av0.w, aph[p0 + 1][am], apl[p0 + 1][am]);
        pack_hl(av1.x, av1.y, aph[p0 + 2][am], apl[p0 + 2][am]);
        pack_hl(av1.z, av1.w, aph[p0 + 3][am], apl[p0 + 3][am]);
        if (j.wfmt == 0) {
#pragma unroll
            for (int r = 0; r < 2; r++) {
                int e = tid + r * 256;
                int kp = e >> 5, n4 = e & 31;
                uint4 hi, lo;
                pack_hl(wv[r * 8 + 0], wv[r * 8 + 4], hi.x, lo.x);
                pack_hl(wv[r * 8 + 1], wv[r * 8 + 5], hi.y, lo.y);
                pack_hl(wv[r * 8 + 2], wv[r * 8 + 6], hi.z, lo.z);
                pack_hl(wv[r * 8 + 3], wv[r * 8 + 7], hi.w, lo.w);
                *(uint4*)&wph[kp][n4 * 4] = hi;
                *(uint4*)&wpl[kp][n4 * 4] = lo;
            }
        } else {
            // lane holds k = lane; even lanes pack (k, k+1) via shfl
#pragma unroll
            for (int i = 0; i < 16; i++) {
                float v = wv[i];
                float v2 = __shfl_down_sync(0xffffffffu, v, 1);
                if ((lane & 1) == 0) {
                    uint32_t hi, lo;
                    pack_hl(v, v2, hi, lo);
                    int kp = lane >> 1;           // 0..15
                    int n = warp * 16 + i;        // 0..127
                    wph[kp][n] = hi;
                    wpl[kp][n] = lo;
                }
            }
        }
    };

    // ---- compute on a smem buffer ----
    auto compute = [&](int buf) {
        A72 aph = (A72)(sm + buf * 16 * 72);
        A72 apl = (A72)(sm + 2304 + buf * 16 * 72);
        W136 wph = (W136)(sm + 4608 + buf * 16 * 136);
        W136 wpl = (W136)(sm + 8960 + buf * 16 * 136);
#pragma unroll
        for (int st = 0; st < 2; st++) {
            int kr = st * 8;
            int mrow = wm * 16 + g;
            uint32_t a0h = aph[kr + tg][mrow];
            uint32_t a1h = aph[kr + tg][mrow + 8];
            uint32_t a2h = aph[kr + tg + 4][mrow];
            uint32_t a3h = aph[kr + tg + 4][mrow + 8];
            uint32_t a0l = apl[kr + tg][mrow];
            uint32_t a1l = apl[kr + tg][mrow + 8];
            uint32_t a2l = apl[kr + tg + 4][mrow];
            uint32_t a3l = apl[kr + tg + 4][mrow + 8];
#pragma unroll
            for (int jt = 0; jt < 8; jt++) {
                int col = wn * 64 + jt * 8 + g;
                uint32_t b0h = wph[kr + tg][col];
                uint32_t b1h = wph[kr + tg + 4][col];
                uint32_t b0l = wpl[kr + tg][col];
                uint32_t b1l = wpl[kr + tg + 4][col];
                mma_bf16(acc[jt], a0h, a1h, a2h, a3h, b0h, b1h);
                mma_bf16(acc[jt], a0h, a1h, a2h, a3h, b0l, b1l);
                mma_bf16(acc[jt], a0l, a1l, a2l, a3l, b0h, b1h);
            }
        }
    };

    load(k0);
    store(0);
    __syncthreads();
    for (int s = 0; s < nst; s++) {
        if (s + 1 < nst) load(k0 + (s + 1) * 32);
        compute(s & 1);
        if (s + 1 < nst) {
            store((s + 1) & 1);
            __syncthreads();
        }
    }

    // ---- write partials ----
#pragma unroll
    for (int jt = 0; jt < 8; jt++) {
        int col = n0 + wn * 64 + jt * 8 + tg * 2;
        int row0 = wm * 16 + g;
        *(float2*)(P + (size_t)row0 * j.N + col) = make_float2(acc[jt][0], acc[jt][1]);
        *(float2*)(P + (size_t)(row0 + 8) * j.N + col) = make_float2(acc[jt][2], acc[jt][3]);
    }
}

// ---------------- float4 split-K reduce + epilogue, tri-job ----------------
struct RJob {
    const float4* P; int np;
    const float4* bias; float4* C;
    int mode; const float4* R; int N4;
};

__global__ __launch_bounds__(256) void reduce_k(RJob r0, RJob r1, RJob r2) {
    RJob r = (blockIdx.z == 0) ? r0 : (blockIdx.z == 1 ? r1 : r2);
    int idx = blockIdx.x * 256 + threadIdx.x;
    int total = 64 * r.N4;
    if (idx >= total) return;
    int n4 = idx % r.N4;
    float4 s = make_float4(0.f, 0.f, 0.f, 0.f);
#pragma unroll 8
    for (int p = 0; p < r.np; p++) {
        float4 v = r.P[(size_t)p * total + idx];
        s.x += v.x; s.y += v.y; s.z += v.z; s.w += v.w;
    }
    float4 b = r.bias[n4];
    s.x += b.x; s.y += b.y; s.z += b.z; s.w += b.w;
    if (r.mode == 1) {
        s.x = siluf_(s.x); s.y = siluf_(s.y); s.z = siluf_(s.z); s.w = siluf_(s.w);
    } else if (r.mode == 2) {
        s.x = sigmoidf_(s.x); s.y = sigmoidf_(s.y); s.z = sigmoidf_(s.z); s.w = sigmoidf_(s.w);
    } else if (r.mode == 3) {
        float4 rv = r.R[idx];
        s.x += rv.x; s.y += rv.y; s.z += rv.z; s.w += rv.w;
    }
    r.C[idx] = s;
}

// ---------------- block-diagonal q/k/v GEMMs + fused i/f gates ----------------
// grid (4, 2, 32): z<24 -> qkv (which=z>>3, h=z&7, 32x64 tile); z>=24 -> gates for
// batch b = (z-24)*8 + blockIdx.y*4 + blockIdx.x. 128 threads.
__global__ __launch_bounds__(128) void qkv_kernel(const float* __restrict__ Wq,
                                                  const float* __restrict__ Wk,
                                                  const float* __restrict__ Wv,
                                                  const float* __restrict__ bq,
                                                  const float* __restrict__ bk,
                                                  const float* __restrict__ bv,
                                                  const float* __restrict__ Wi,
                                                  const float* __restrict__ bi,
                                                  const float* __restrict__ Wf,
                                                  const float* __restrict__ bf,
                                                  const float* __restrict__ m_prev,
                                                  float* __restrict__ m_out) {
    int z = blockIdx.z;
    if (z >= 24) {
        int b = (z - 24) * 8 + blockIdx.y * 4 + blockIdx.x;
        int t = threadIdx.x;
        float pi[8] = {}, pf[8] = {};
        for (int k = t; k < NHID; k += 128) {
            float xv = g_xc[b * NHID + k];
            const float4* wi4 = (const float4*)(Wi + k * 8);
            const float4* wf4 = (const float4*)(Wf + k * 8);
            float4 a0 = wi4[0], a1 = wi4[1], f0 = wf4[0], f1 = wf4[1];
            pi[0] += xv * a0.x; pi[1] += xv * a0.y; pi[2] += xv * a0.z; pi[3] += xv * a0.w;
            pi[4] += xv * a1.x; pi[5] += xv * a1.y; pi[6] += xv * a1.z; pi[7] += xv * a1.w;
            pf[0] += xv * f0.x; pf[1] += xv * f0.y; pf[2] += xv * f0.z; pf[3] += xv * f0.w;
            pf[4] += xv * f1.x; pf[5] += xv * f1.y; pf[6] += xv * f1.z; pf[7] += xv * f1.w;
        }
        __shared__ float s[128 * 16];
#pragma unroll
        for (int h = 0; h < 8; h++) { s[t * 16 + h] = pi[h]; s[t * 16 + 8 + h] = pf[h]; }
        __syncthreads();
        if (t < 16) {
            float a = 0.f;
            for (int r = 0; r < 128; r++) a += s[r * 16 + t];
            s[t] = a;
        }
        __syncthreads();
        if (t < 8) {
            float it = s[t] + bi[t];
            float ft = s[8 + t] + bf[t];
            float mp = m_prev[b * 8 + t];
            float m = fmaxf(ft + mp, it);
            m_out[b * 8 + t] = m;
            g_ig[b * 8 + t] = expf(it - m);
            g_fg[b * 8 + t] = expf(ft + mp - m);
        }
        return;
    }
    int which = z >> 3, h = z & 7;
    const float* A = (which == 2) ? g_xl : g_xc;
    const float* W; const float* bias; float* C; float scale = 1.f;
    if (which == 0) { W = Wq; bias = bq; C = g_q; }
    else if (which == 1) { W = Wk; bias = bk; C = g_k; scale = 0.0625f; }
    else { W = Wv; bias = bv; C = g_v; }
    W += (size_t)h * ND * ND;
    bias += h * ND;
    int n0 = blockIdx.x * 64;
    int m0 = blockIdx.y * 32;
    __shared__ __align__(16) float As[32][36];
    __shared__ __align__(16) float Ws[32][68];
    int tx = threadIdx.x & 15, ty = threadIdx.x >> 4;
    float acc[4][4] = {};
    for (int kb = 0; kb < ND; kb += 32) {
#pragma unroll
        for (int r = 0; r < 2; r++) {
            int ee = threadIdx.x + r * 128;
            int k4 = ee & 7, m = ee >> 3;
            float4 v = *(const float4*)(A + (size_t)(m0 + m) * NHID + h * ND + kb + 4 * k4);
            *(float4*)&As[m][4 * k4] = v;
        }
#pragma unroll
        for (int r = 0; r < 4; r++) {
            int ee = threadIdx.x + r * 128;
            int n4 = ee & 15, k = ee >> 4;
            float4 v = *(const float4*)(W + (size_t)(kb + k) * ND + n0 + 4 * n4);
            *(float4*)&Ws[k][4 * n4] = v;
        }
        __syncthreads();
#pragma unroll
        for (int kk = 0; kk < 32; kk++) {
            float4 w = *(const float4*)&Ws[kk][tx * 4];
            float a0 = As[ty * 4 + 0][kk];
            float a1 = As[ty * 4 + 1][kk];
            float a2 = As[ty * 4 + 2][kk];
            float a3 = As[ty * 4 + 3][kk];
            acc[0][0] += a0 * w.x; acc[0][1] += a0 * w.y; acc[0][2] += a0 * w.z; acc[0][3] += a0 * w.w;
            acc[1][0] += a1 * w.x; acc[1][1] += a1 * w.y; acc[1][2] += a1 * w.z; acc[1][3] += a1 * w.w;
            acc[2][0] += a2 * w.x; acc[2][1] += a2 * w.y; acc[2][2] += a2 * w.z; acc[2][3] += a2 * w.w;
            acc[3][0] += a3 * w.x; acc[3][1] += a3 * w.y; acc[3][2] += a3 * w.z; acc[3][3] += a3 * w.w;
        }
        __syncthreads();
    }
#pragma unroll
    for (int i = 0; i < 4; i++) {
        int m = m0 + ty * 4 + i;
        int n = n0 + tx * 4;
        float4 b4 = *(const float4*)(bias + n);
        float4 v = make_float4((acc[i][0] + b4.x) * scale, (acc[i][1] + b4.y) * scale,
                               (acc[i][2] + b4.z) * scale, (acc[i][3] + b4.w) * scale);
        *(float4*)(C + (size_t)m * NHID + h * ND + n) = v;
    }
}

// ---------------- fused state update + readout + GroupNorm + gating ----------------
__global__ __launch_bounds__(256) void state_kernel(const float* __restrict__ c_prev,
                                                    const float* __restrict__ n_prev,
                                                    const float* __restrict__ gn_w,
                                                    const float* __restrict__ gn_b,
                                                    float* __restrict__ c_out,
                                                    float* __restrict__ n_out,
                                                    float* __restrict__ h_out) {
    int bh = blockIdx.x;
    int b = bh >> 3, h = bh & 7;
    int t = threadIdx.x;
    __shared__ __align__(16) float qs[256], ks[256], vs[256], hts[256];
    __shared__ float den_s;
    float fg = g_fg[bh], ig = g_ig[bh];
    int base = bh * ND;
    float qv = g_q[base + t], kv = g_k[base + t], vv = g_v[base + t];
    qs[t] = qv; ks[t] = kv; vs[t] = vv;
    float nt = fg * n_prev[base + t] + ig * kv;
    n_out[base + t] = nt;
    float den = blockReduce256(nt * qv);
    if (t == 0) den_s = fmaxf(den, 1.f);
    __syncthreads();
    den = den_s;
    int w = t >> 5, lane = t & 31;
    const float4* cp4 = (const float4*)(c_prev + (size_t)bh * ND * ND);
    float4* ct4 = (float4*)(c_out + (size_t)bh * ND * ND);
    const float4* qs4 = (const float4*)qs;
    const float4* ks4 = (const float4*)ks;
    int ci0 = lane, ci1 = lane + 32;
    float4 kk0 = ks4[ci0], kk1 = ks4[ci1];
    float4 qq0 = qs4[ci0], qq1 = qs4[ci1];
    for (int d0 = w * 32; d0 < w * 32 + 32; d0 += 4) {
        float vd0 = vs[d0 + 0] * ig, vd1 = vs[d0 + 1] * ig;
        float vd2 = vs[d0 + 2] * ig, vd3 = vs[d0 + 3] * ig;
        // front-batch all 8 c_prev loads (MLP 8)
        float4 a0 = cp4[(size_t)(d0 + 0) * 64 + ci0];
        float4 a1 = cp4[(size_t)(d0 + 1) * 64 + ci0];
        float4 a2 = cp4[(size_t)(d0 + 2) * 64 + ci0];
        float4 a3 = cp4[(size_t)(d0 + 3) * 64 + ci0];
        float4 b0 = cp4[(size_t)(d0 + 0) * 64 + ci1];
        float4 b1 = cp4[(size_t)(d0 + 1) * 64 + ci1];
        float4 b2 = cp4[(size_t)(d0 + 2) * 64 + ci1];
        float4 b3 = cp4[(size_t)(d0 + 3) * 64 + ci1];
        float4 c0, c1, c2, c3, d1, d2, d3, d4;
        c0.x = fg * a0.x + vd0 * kk0.x; c0.y = fg * a0.y + vd0 * kk0.y;
        c0.z = fg * a0.z + vd0 * kk0.z; c0.w = fg * a0.w + vd0 * kk0.w;
        c1.x = fg * a1.x + vd1 * kk0.x; c1.y = fg * a1.y + vd1 * kk0.y;
        c1.z = fg * a1.z + vd1 * kk0.z; c1.w = fg * a1.w + vd1 * kk0.w;
        c2.x = fg * a2.x + vd2 * kk0.x; c2.y = fg * a2.y + vd2 * kk0.y;
        c2.z = fg * a2.z + vd2 * kk0.z; c2.w = fg * a2.w + vd2 * kk0.w;
        c3.x = fg * a3.x + vd3 * kk0.x; c3.y = fg * a3.y + vd3 * kk0.y;
        c3.z = fg * a3.z + vd3 * kk0.z; c3.w = fg * a3.w + vd3 * kk0.w;
        d1.x = fg * b0.x + vd0 * kk1.x; d1.y = fg * b0.y + vd0 * kk1.y;
        d1.z = fg * b0.z + vd0 * kk1.z; d1.w = fg * b0.w + vd0 * kk1.w;
        d2.x = fg * b1.x + vd1 * kk1.x; d2.y = fg * b1.y + vd1 * kk1.y;
        d2.z = fg * b1.z + vd1 * kk1.z; d2.w = fg * b1.w + vd1 * kk1.w;
        d3.x = fg * b2.x + vd2 * kk1.x; d3.y = fg * b2.y + vd2 * kk1.y;
        d3.z = fg * b2.z + vd2 * kk1.z; d3.w = fg * b2.w + vd2 * kk1.w;
        d4.x = fg * b3.x + vd3 * kk1.x; d4.y = fg * b3.y + vd3 * kk1.y;
        d4.z = fg * b3.z + vd3 * kk1.z; d4.w = fg * b3.w + vd3 * kk1.w;
        ct4[(size_t)(d0 + 0) * 64 + ci0] = c0;
        ct4[(size_t)(d0 + 1) * 64 + ci0] = c1;
        ct4[(size_t)(d0 + 2) * 64 + ci0] = c2;
        ct4[(size_t)(d0 + 3) * 64 + ci0] = c3;
        ct4[(size_t)(d0 + 0) * 64 + ci1] = d1;
        ct4[(size_t)(d0 + 1) * 64 + ci1] = d2;
        ct4[(size_t)(d0 + 2) * 64 + ci1] = d3;
        ct4[(size_t)(d0 + 3) * 64 + ci1] = d4;
        float acc0 = c0.x * qq0.x + c0.y * qq0.y + c0.z * qq0.z + c0.w * qq0.w
                   + d1.x * qq1.x + d1.y * qq1.y + d1.z * qq1.z + d1.w * qq1.w;
        float acc1 = c1.x * qq0.x + c1.y * qq0.y + c1.z * qq0.z + c1.w * qq0.w
                   + d2.x * qq1.x + d2.y * qq1.y + d2.z * qq1.z + d2.w * qq1.w;
        float acc2 = c2.x * qq0.x + c2.y * qq0.y + c2.z * qq0.z + c2.w * qq0.w
                   + d3.x * qq1.x + d3.y * qq1.y + d3.z * qq1.z + d3.w * qq1.w;
        float acc3 = c3.x * qq0.x + c3.y * qq0.y + c3.z * qq0.z + c3.w * qq0.w
                   + d4.x * qq1.x + d4.y * qq1.y + d4.z * qq1.z + d4.w * qq1.w;
#pragma unroll
        for (int off = 16; off > 0; off >>= 1) {
            acc0 += __shfl_xor_sync(0xffffffffu, acc0, off);
            acc1 += __shfl_xor_sync(0xffffffffu, acc1, off);
            acc2 += __shfl_xor_sync(0xffffffffu, acc2, off);
            acc3 += __shfl_xor_sync(0xffffffffu, acc3, off);
        }
        if (lane == 0) {
            float h0 = g_o[base + d0 + 0] * acc0 / den;
            float h1 = g_o[base + d0 + 1] * acc1 / den;
            float h2 = g_o[base + d0 + 2] * acc2 / den;
            float h3 = g_o[base + d0 + 3] * acc3 / den;
            hts[d0 + 0] = h0; hts[d0 + 1] = h1; hts[d0 + 2] = h2; hts[d0 + 3] = h3;
            h_out[base + d0 + 0] = h0; h_out[base + d0 + 1] = h1;
            h_out[base + d0 + 2] = h2; h_out[base + d0 + 3] = h3;
        }
    }
    __syncthreads();
    float hv = hts[t];
    float mu = blockReduce256(hv) * (1.f / ND);
    float dv = hv - mu;
    float var = blockReduce256(dv * dv) * (1.f / ND);
    float g = dv * rsqrtf(var + EPS);
    int hid = h * ND + t;
    float xrv = g_xr[b * NHID + hid];
    g_outpre[b * NHID + hid] =
        (g * gn_w[hid] + gn_b[hid] + g_xskip[b * NHID + hid]) * siluf_(xrv);
}

// ---------------- stream/event aux ----------------
struct Aux {
    cudaStream_t s2;
    cudaEvent_t evFork, evJoin;
};
static Aux make_aux() {
    Aux a;
    cudaStreamCreateWithFlags(&a.s2, cudaStreamNonBlocking);
    cudaEventCreateWithFlags(&a.evFork, cudaEventDisableTiming);
    cudaEventCreateWithFlags(&a.evJoin, cudaEventDisableTiming);
    return a;
}

// ---------------- host launcher ----------------
extern "C" void kernel_launch(void* const* d_in, const int* in_sizes, int n_in,
                              void* d_out, int out_size) {
    (void)in_sizes; (void)n_in; (void)out_size;
    static Aux aux = make_aux();

    const float* x      = (const float*)d_in[0];
    const float* c_prev = (const float*)d_in[2];
    const float* n_prev = (const float*)d_in[3];
    const float* m_prev = (const float*)d_in[4];
    const float* ln_w   = (const float*)d_in[5];
    const float* ln_b   = (const float*)d_in[6];
    const float* W_ul   = (const float*)d_in[7];
    const float* b_ul   = (const float*)d_in[8];
    const float* W_ur   = (const float*)d_in[9];
    const float* b_ur   = (const float*)d_in[10];
    const float* W_conv = (const float*)d_in[11];
    const float* b_conv = (const float*)d_in[12];
    const float* W_skip = (const float*)d_in[13];
    const float* b_skip = (const float*)d_in[14];
    const float* W_q    = (const float*)d_in[15];
    const float* b_q    = (const float*)d_in[16];
    const float* W_k    = (const float*)d_in[17];
    const float* b_k    = (const float*)d_in[18];
    const float* W_v    = (const float*)d_in[19];
    const float* b_v    = (const float*)d_in[20];
    const float* W_i    = (const float*)d_in[21];
    const float* b_i    = (const float*)d_in[22];
    const float* W_f    = (const float*)d_in[23];
    const float* b_f    = (const float*)d_in[24];
    const float* W_o    = (const float*)d_in[25];
    const float* b_o    = (const float*)d_in[26];
    const float* W_down = (const float*)d_in[27];
    const float* b_down = (const float*)d_in[28];
    const float* gn_w   = (const float*)d_in[29];
    const float* gn_b   = (const float*)d_in[30];

    float* out = (float*)d_out;
    float* out_final = out;
    float* out_h = out + NB * NI;
    float* out_c = out_h + NB * NH * ND;
    float* out_n = out_c + (size_t)NB * NH * ND * ND;
    float* out_m = out_n + NB * NH * ND;

    void *p_xn, *p_xl, *p_xr, *p_xc, *p_xskip, *p_o, *p_outpre, *p_part;
    cudaGetSymbolAddress(&p_xn, g_xn);
    cudaGetSymbolAddress(&p_xl, g_xl);
    cudaGetSymbolAddress(&p_xr, g_xr);
    cudaGetSymbolAddress(&p_xc, g_xc);
    cudaGetSymbolAddress(&p_xskip, g_xskip);
    cudaGetSymbolAddress(&p_o, g_o);
    cudaGetSymbolAddress(&p_outpre, g_outpre);
    cudaGetSymbolAddress(&p_part, g_part);
    float* xn = (float*)p_xn;
    float* xl = (float*)p_xl;
    float* xr = (float*)p_xr;
    float* xc = (float*)p_xc;
    float* xskip = (float*)p_xskip;
    float* o = (float*)p_o;
    float* outpre = (float*)p_outpre;
    float* part = (float*)p_part;

    const int SLOT = NB * NHID;   // 131072 floats per [64 x 2048] partial slot
    const int SMEM_BYTES = SMEM_WORDS * 4;   // 53248
    cudaFuncSetAttribute(gemm_t, cudaFuncAttributeMaxDynamicSharedMemorySize, SMEM_BYTES);

    // 1. LayerNorm
    ln_kernel<<<NB, 256>>>(x, ln_w, ln_b);

    // 2. ul + ur dual (8-way each, 256 blocks = 1 wave), dual reduce
    {
        GJob a{xn, W_ul, part, NI, 128, NHID, 0};                          // slots 0-7
        GJob b2{xn, W_ur, part + (size_t)8 * SLOT, NI, 128, NHID, 0};      // slots 8-15
        gemm_t<<<dim3(16, 8, 2), 256, SMEM_BYTES>>>(a, b2, b2);
        RJob ra{(const float4*)part, 8, (const float4*)b_ul, (float4*)xl, 0, nullptr, NHID / 4};
        RJob rb{(const float4*)(part + (size_t)8 * SLOT), 8, (const float4*)b_ur, (float4*)xr, 0, nullptr, NHID / 4};
        reduce_k<<<dim3(128, 1, 2), 256>>>(ra, rb, rb);
    }

    // 3. conv (tap-3) ALONE: 16-way split, 256 blocks = full dedicated wave
    {
        GJob a{xl, W_conv, part, NHID, 128, NHID, 1};                      // slots 0-15
        gemm_t<<<dim3(16, 16, 1), 256, SMEM_BYTES>>>(a, a, a);
        RJob ra{(const float4*)part, 16, (const float4*)b_conv, (float4*)xc, 1, nullptr, NHID / 4};
        reduce_k<<<dim3(128, 1, 1), 256>>>(ra, ra, ra);
    }

    // ---- fork: qkv (+gates) on side stream; overlaps skip+o gemm+reduce ----
    cudaEventRecord(aux.evFork, 0);
    cudaStreamWaitEvent(aux.s2, aux.evFork, 0);
    qkv_kernel<<<dim3(4, 2, 32), 128, 0, aux.s2>>>(W_q, W_k, W_v, b_q, b_k, b_v,
                                                   W_i, b_i, W_f, b_f, m_prev, out_m);
    cudaEventRecord(aux.evJoin, aux.s2);

    // 4. skip + o dual (8-way each, 256 blocks), dual reduce
    {
        GJob a{xc, W_skip, part, NHID, 256, NHID, 0};                      // slots 0-7
        GJob b2{xl, W_o, part + (size_t)8 * SLOT, NHID, 256, NHID, 0};     // slots 8-15
        gemm_t<<<dim3(16, 8, 2), 256, SMEM_BYTES>>>(a, b2, b2);
        RJob ra{(const float4*)part, 8, (const float4*)b_skip, (float4*)xskip, 0, nullptr, NHID / 4};
        RJob rb{(const float4*)(part + (size_t)8 * SLOT), 8, (const float4*)b_o, (float4*)o, 2, nullptr, NHID / 4};
        reduce_k<<<dim3(128, 1, 2), 256>>>(ra, rb, rb);
    }

    // ---- join before state (needs q/k/v/ig/fg) ----
    cudaStreamWaitEvent(0, aux.evJoin, 0);

    // 5. fused state update / readout / groupnorm / gating
    state_kernel<<<NB * NH, 256>>>(c_prev, n_prev, gn_w, gn_b, out_c, out_n, out_h);

    // 6. final = outpre @ W_down + b_down + x : K=2048, 32-way split, N=1024
    {
        GJob a{outpre, W_down, part, NHID, 64, NI, 0};
        gemm_t<<<dim3(8, 32, 1), 256, SMEM_BYTES>>>(a, a, a);
        RJob ra{(const float4*)part, 32, (const float4*)b_down, (float4*)out_final, 3, (const float4*)x, NI / 4};
        reduce_k<<<dim3(64, 1, 1), 256>>>(ra, ra, ra);
    }
}